// round 5
// baseline (speedup 1.0000x reference)
#include <cuda_runtime.h>
#include <cstdint>
#include <math.h>
#include <mma.h>

using namespace nvcuda;

#define NN 100000
#define EE 150000
#define DD 512
#define HH 8

#define GBM 128
#define GBN 128
#define GBK 32
#define APAD 8   // A row stride 40 floats (160B, keeps 16B alignment)
#define BPAD 8   // B row stride 136 floats (544B)

#define A_STAGE (GBM * (GBK + APAD))   // 5120 floats
#define B_STAGE (GBK * (GBN + BPAD))   // 4352 floats
#define OFF_AS0 0
#define OFF_AS1 (A_STAGE)
#define OFF_BS0 (2 * A_STAGE)
#define OFF_BS1 (2 * A_STAGE + B_STAGE)
#define OFF_STG (2 * A_STAGE + 2 * B_STAGE)          // 8 warps * 16*20
#define OFF_KS  (OFF_STG + 8 * 16 * 20)
#define SMEM_FLOATS (OFF_KS + GBN)
#define SMEM_BYTES (SMEM_FLOATS * 4)                  // 86528

// ---------------- scratch ---------------------------------------------------
__device__ float g_h_o[(size_t)NN * DD];
__device__ float g_h_e[(size_t)NN * DD];
__device__ float g_out0[(size_t)NN * DD];
__device__ float g_out1[(size_t)NN * DD];
__device__ float g_a_se[NN * HH];   // att_src_e2o dot (from h_e)
__device__ float g_a_de[NN * HH];   // att_dst_e2o dot (from h_o)
__device__ float g_a_so[NN * HH];   // att_src_o2o dot (from h_o)
__device__ float g_a_do[NN * HH];   // att_dst_o2o dot (from h_o)
__device__ unsigned g_amax[NN * HH];
__device__ float g_denom[NN * HH];
__device__ float g_ebuf[EE * HH];
__device__ float g_ksum[2 * DD];
__device__ float g_musum[2 * DD];

// ---------------- helpers ---------------------------------------------------
__device__ __forceinline__ unsigned mapf(float f) {
    unsigned u = __float_as_uint(f);
    return (u & 0x80000000u) ? ~u : (u | 0x80000000u);
}
__device__ __forceinline__ float unmapf(unsigned u) {
    return __uint_as_float((u & 0x80000000u) ? (u & 0x7FFFFFFFu) : ~u);
}

__device__ __forceinline__ void cp16(uint32_t dst, const float* src, bool full) {
    int sz = full ? 16 : 0;
    asm volatile("cp.async.cg.shared.global [%0], [%1], 16, %2;"
                 :: "r"(dst), "l"(src), "r"(sz));
}

__global__ void zero_buf(float* p, long n) {
    long i = (long)blockIdx.x * blockDim.x + threadIdx.x;
    long stride = (long)gridDim.x * blockDim.x;
    for (; i < n; i += stride) p[i] = 0.0f;
}

__global__ void init_edge_state(unsigned* amax, float* denom, int n) {
    int i = blockIdx.x * blockDim.x + threadIdx.x;
    if (i < n) { amax[i] = 0x007FFFFFu; denom[i] = 0.0f; }  // mapf(-inf)
}

// ---------------- TF32 TC GEMM, 2-stage cp.async pipeline -------------------
// MODE 0: C = A@W + bias (stored).
// MODE 1: relu(A) applied in-register; epilogue accumulates
//         sum_rows tanh(acc+bias) into ksum_out (C not written).
template <int MODE>
__global__ void __launch_bounds__(256) gemm_tc(
        const float* __restrict__ A, const float* __restrict__ W,
        const float* __restrict__ bias, float* __restrict__ C, int M,
        float* __restrict__ ksum_out) {
    extern __shared__ float smem[];
    float* AsBase[2] = {smem + OFF_AS0, smem + OFF_AS1};
    float* BsBase[2] = {smem + OFF_BS0, smem + OFF_BS1};
    float* stg = smem + OFF_STG;
    float* ksred = smem + OFF_KS;

    int tid = threadIdx.x;
    int wid = tid >> 5;
    int lane = tid & 31;
    int warp_m = wid & 3;
    int warp_n = wid >> 2;
    int m0 = blockIdx.y * GBM;
    int n0 = blockIdx.x * GBN;
    int wm0 = warp_m * 32;
    int wn0 = warp_n * 64;

    if (MODE == 1 && tid < GBN) ksred[tid] = 0.0f;

    // per-thread load coordinates (4 chunks of 16B per tile per thread)
    int a_row[4], a_c4[4], b_row[4], b_c4[4];
#pragma unroll
    for (int it = 0; it < 4; it++) {
        int idx = tid + it * 256;
        a_row[it] = idx >> 3;  a_c4[it] = (idx & 7) << 2;
        b_row[it] = idx >> 5;  b_c4[it] = (idx & 31) << 2;
    }

    auto load_stage = [&](int s, int k0) {
#pragma unroll
        for (int it = 0; it < 4; it++) {
            int gm = m0 + a_row[it];
            bool ok = gm < M;
            const float* src = A + (size_t)(ok ? gm : 0) * DD + k0 + a_c4[it];
            uint32_t dst = (uint32_t)__cvta_generic_to_shared(
                AsBase[s] + a_row[it] * (GBK + APAD) + a_c4[it]);
            cp16(dst, src, ok);
        }
#pragma unroll
        for (int it = 0; it < 4; it++) {
            const float* src = W + (size_t)(k0 + b_row[it]) * DD + n0 + b_c4[it];
            uint32_t dst = (uint32_t)__cvta_generic_to_shared(
                BsBase[s] + b_row[it] * (GBN + BPAD) + b_c4[it]);
            cp16(dst, src, true);
        }
    };

    wmma::fragment<wmma::accumulator, 16, 16, 8, float> acc[2][4];
#pragma unroll
    for (int i = 0; i < 2; i++)
#pragma unroll
        for (int j = 0; j < 4; j++) wmma::fill_fragment(acc[i][j], 0.0f);

    load_stage(0, 0);
    asm volatile("cp.async.commit_group;");

    int stage = 0;
    for (int k0 = 0; k0 < DD; k0 += GBK) {
        if (k0 + GBK < DD) load_stage(stage ^ 1, k0 + GBK);
        asm volatile("cp.async.commit_group;");
        asm volatile("cp.async.wait_group 1;");
        __syncthreads();

        const float* As = AsBase[stage];
        const float* Bs = BsBase[stage];
#pragma unroll
        for (int kk = 0; kk < GBK; kk += 8) {
            wmma::fragment<wmma::matrix_a, 16, 16, 8, wmma::precision::tf32,
                           wmma::row_major> af[2];
            wmma::fragment<wmma::matrix_b, 16, 16, 8, wmma::precision::tf32,
                           wmma::row_major> bf[4];
#pragma unroll
            for (int i = 0; i < 2; i++) {
                wmma::load_matrix_sync(af[i], As + (wm0 + i * 16) * (GBK + APAD) + kk,
                                       GBK + APAD);
#pragma unroll
                for (int t = 0; t < af[i].num_elements; t++) {
                    float x = af[i].x[t];
                    if (MODE == 1) x = fmaxf(x, 0.0f);
                    af[i].x[t] = wmma::__float_to_tf32(x);
                }
            }
#pragma unroll
            for (int j = 0; j < 4; j++) {
                wmma::load_matrix_sync(bf[j], Bs + kk * (GBN + BPAD) + wn0 + j * 16,
                                       GBN + BPAD);
#pragma unroll
                for (int t = 0; t < bf[j].num_elements; t++)
                    bf[j].x[t] = wmma::__float_to_tf32(bf[j].x[t]);
            }
#pragma unroll
            for (int i = 0; i < 2; i++)
#pragma unroll
                for (int j = 0; j < 4; j++)
                    wmma::mma_sync(acc[i][j], af[i], bf[j], acc[i][j]);
        }
        __syncthreads();
        stage ^= 1;
    }

    // ---------------- epilogue ----------------
    float* mystg = stg + wid * 320;   // 16x20
    int r = lane >> 1;
    int cbase = (lane & 1) * 8;
#pragma unroll
    for (int i = 0; i < 2; i++) {
#pragma unroll
        for (int j = 0; j < 4; j++) {
            wmma::store_matrix_sync(mystg, acc[i][j], 20, wmma::mem_row_major);
            __syncwarp();
            int grow = m0 + wm0 + i * 16 + r;
            int gcol = n0 + wn0 + j * 16 + cbase;
            if (grow < M) {
                float4 v1 = *(const float4*)(mystg + r * 20 + cbase);
                float4 v2 = *(const float4*)(mystg + r * 20 + cbase + 4);
                float4 b1 = *(const float4*)(bias + gcol);
                float4 b2 = *(const float4*)(bias + gcol + 4);
                v1.x += b1.x; v1.y += b1.y; v1.z += b1.z; v1.w += b1.w;
                v2.x += b2.x; v2.y += b2.y; v2.z += b2.z; v2.w += b2.w;
                if (MODE == 0) {
                    *(float4*)(C + (size_t)grow * DD + gcol) = v1;
                    *(float4*)(C + (size_t)grow * DD + gcol + 4) = v2;
                } else {
                    int lc = wn0 + j * 16 + cbase;
                    atomicAdd(&ksred[lc + 0], tanhf(v1.x));
                    atomicAdd(&ksred[lc + 1], tanhf(v1.y));
                    atomicAdd(&ksred[lc + 2], tanhf(v1.z));
                    atomicAdd(&ksred[lc + 3], tanhf(v1.w));
                    atomicAdd(&ksred[lc + 4], tanhf(v2.x));
                    atomicAdd(&ksred[lc + 5], tanhf(v2.y));
                    atomicAdd(&ksred[lc + 6], tanhf(v2.z));
                    atomicAdd(&ksred[lc + 7], tanhf(v2.w));
                }
            }
            __syncwarp();
        }
    }
    if (MODE == 1) {
        __syncthreads();
        if (tid < GBN) atomicAdd(&ksum_out[n0 + tid], ksred[tid]);
    }
}

// ---------------- attention dots: 1 read of h, up to 3 att pairs ------------
__global__ void compute_ah3(const float* __restrict__ hmat,
                            const float* __restrict__ att0, float* __restrict__ a0,
                            const float* __restrict__ att1, float* __restrict__ a1,
                            const float* __restrict__ att2, float* __restrict__ a2,
                            int n_nodes) {
    int gt = blockIdx.x * blockDim.x + threadIdx.x;
    int warp = gt >> 5;
    int lane = threadIdx.x & 31;
    if (warp >= n_nodes) return;
    int base = lane * 16;
    const float4* hp = (const float4*)(hmat + (size_t)warp * DD + base);
    const float4* ap0 = (const float4*)(att0 + base);
    const float4* ap1 = att1 ? (const float4*)(att1 + base) : nullptr;
    const float4* ap2 = att2 ? (const float4*)(att2 + base) : nullptr;
    float s0 = 0.f, s1 = 0.f, s2 = 0.f;
#pragma unroll
    for (int q = 0; q < 4; q++) {
        float4 hv = hp[q];
        float4 av = ap0[q];
        s0 += hv.x * av.x + hv.y * av.y + hv.z * av.z + hv.w * av.w;
        if (ap1) {
            float4 bv = ap1[q];
            s1 += hv.x * bv.x + hv.y * bv.y + hv.z * bv.z + hv.w * bv.w;
        }
        if (ap2) {
            float4 cv = ap2[q];
            s2 += hv.x * cv.x + hv.y * cv.y + hv.z * cv.z + hv.w * cv.w;
        }
    }
#pragma unroll
    for (int d = 1; d <= 2; d <<= 1) {
        s0 += __shfl_xor_sync(0xffffffffu, s0, d);
        s1 += __shfl_xor_sync(0xffffffffu, s1, d);
        s2 += __shfl_xor_sync(0xffffffffu, s2, d);
    }
    if ((lane & 3) == 0) {
        int o = warp * HH + (lane >> 2);
        a0[o] = s0;
        if (a1) a1[o] = s1;
        if (a2) a2[o] = s2;
    }
}

// ---------------- edge pass 1: alpha + segment max --------------------------
__global__ void edge_alpha_max(const int* __restrict__ src,
                               const int* __restrict__ dst,
                               const float* __restrict__ asrc,
                               const float* __restrict__ adst,
                               float* __restrict__ alpha,
                               unsigned* __restrict__ amax, int ne) {
    int i = blockIdx.x * blockDim.x + threadIdx.x;
    if (i >= ne * HH) return;
    int e = i >> 3, h = i & 7;
    float v = asrc[src[e] * HH + h] + adst[dst[e] * HH + h];
    v = (v > 0.f) ? v : 0.2f * v;
    alpha[i] = v;
    atomicMax(&amax[dst[e] * HH + h], mapf(v));
}

// ---------------- edge pass 2: exp + segment sum ----------------------------
__global__ void edge_exp_sum(const int* __restrict__ dst,
                             float* __restrict__ alpha,
                             const unsigned* __restrict__ amax,
                             float* __restrict__ denom, int ne) {
    int i = blockIdx.x * blockDim.x + threadIdx.x;
    if (i >= ne * HH) return;
    int e = i >> 3, h = i & 7;
    float ex = expf(alpha[i] - unmapf(amax[dst[e] * HH + h]));
    alpha[i] = ex;
    atomicAdd(&denom[dst[e] * HH + h], ex);
}

// ---------------- edge pass 3: weighted scatter (vector red) ----------------
__global__ void edge_scatter(const int* __restrict__ src,
                             const int* __restrict__ dst,
                             const float* __restrict__ hsrc,
                             const float* __restrict__ exbuf,
                             const float* __restrict__ denom,
                             float* __restrict__ outb, int ne) {
    int gt = blockIdx.x * blockDim.x + threadIdx.x;
    int e = gt >> 5;
    int lane = threadIdx.x & 31;
    if (e >= ne) return;
    int s = src[e], d = dst[e];
    int h = lane >> 2;
    float w = exbuf[e * HH + h] / (denom[d * HH + h] + 1e-16f);
    const float4* hp = (const float4*)(hsrc + (size_t)s * DD + lane * 16);
    float* op = outb + (size_t)d * DD + lane * 16;
#pragma unroll
    for (int q = 0; q < 4; q++) {
        float4 v = hp[q];
        asm volatile("red.global.add.v4.f32 [%0], {%1, %2, %3, %4};"
                     :: "l"(op + q * 4), "f"(v.x * w), "f"(v.y * w),
                        "f"(v.z * w), "f"(v.w * w)
                     : "memory");
    }
}

// ---------------- column means of relu(out) ---------------------------------
__global__ void mu_kernel(const float* __restrict__ outb,
                          float* __restrict__ musum, int M) {
    int f = threadIdx.x;
    int chunk = (M + gridDim.x - 1) / gridDim.x;
    int r0 = blockIdx.x * chunk;
    int r1 = min(M, r0 + chunk);
    float acc = 0.f;
    for (int r = r0; r < r1; r++)
        acc += fmaxf(outb[(size_t)r * DD + f], 0.f);
    atomicAdd(&musum[f], acc);
}

// ---------------- final semantic attention + pool + linear ------------------
__global__ void final_kernel(const float* __restrict__ qsem,
                             const float* __restrict__ linw,
                             const float* __restrict__ linb,
                             float* __restrict__ out) {
    __shared__ float sh[DD];
    __shared__ float sv[2];
    int f = threadIdx.x;
    const float invN = 1.0f / (float)NN;
    float q = qsem[f];
    float v0 = g_ksum[f] * invN * q;
    float v1 = g_ksum[DD + f] * invN * q;

    sh[f] = v0; __syncthreads();
    for (int s = 256; s > 0; s >>= 1) { if (f < s) sh[f] += sh[f + s]; __syncthreads(); }
    if (f == 0) sv[0] = sh[0];
    __syncthreads();
    sh[f] = v1; __syncthreads();
    for (int s = 256; s > 0; s >>= 1) { if (f < s) sh[f] += sh[f + s]; __syncthreads(); }
    if (f == 0) sv[1] = sh[0];
    __syncthreads();

    float s0 = sv[0], s1 = sv[1];
    float mx = fmaxf(s0, s1);
    float e0 = expf(s0 - mx), e1 = expf(s1 - mx);
    float sem0 = e0 / (e0 + e1), sem1 = e1 / (e0 + e1);

    float pooled = (sem0 * g_musum[f] + sem1 * g_musum[DD + f]) * invN;
    float w0 = pooled * linw[f * 2 + 0];
    float w1 = pooled * linw[f * 2 + 1];

    sh[f] = w0; __syncthreads();
    for (int s = 256; s > 0; s >>= 1) { if (f < s) sh[f] += sh[f + s]; __syncthreads(); }
    if (f == 0) out[0] = sh[0] + linb[0];
    __syncthreads();
    sh[f] = w1; __syncthreads();
    for (int s = 256; s > 0; s >>= 1) { if (f < s) sh[f] += sh[f + s]; __syncthreads(); }
    if (f == 0) out[1] = sh[0] + linb[1];
}

// ---------------- host launcher ---------------------------------------------
extern "C" void kernel_launch(void* const* d_in, const int* in_sizes, int n_in,
                              void* d_out, int out_size) {
    const float* x_o  = (const float*)d_in[0];
    const float* x_e  = (const float*)d_in[1];
    const int*   e2o  = (const int*)d_in[2];
    const int*   o2o  = (const int*)d_in[3];
    const float* powm = (const float*)d_in[4];
    const float* pob  = (const float*)d_in[5];
    const float* pewm = (const float*)d_in[6];
    const float* peb  = (const float*)d_in[7];
    const float* a_s_e2o = (const float*)d_in[8];
    const float* a_d_e2o = (const float*)d_in[9];
    const float* a_s_o2o = (const float*)d_in[10];
    const float* a_d_o2o = (const float*)d_in[11];
    const float* klw  = (const float*)d_in[12];
    const float* klb  = (const float*)d_in[13];
    const float* qsem = (const float*)d_in[14];
    const float* linw = (const float*)d_in[15];
    const float* linb = (const float*)d_in[16];
    float* out = (float*)d_out;

    void* p;
    float *h_o, *h_e, *out0, *out1, *a_se, *a_de, *a_so, *a_do, *denom, *ebuf, *ksum, *musum;
    unsigned* amax;
    cudaGetSymbolAddress(&p, g_h_o);  h_o  = (float*)p;
    cudaGetSymbolAddress(&p, g_h_e);  h_e  = (float*)p;
    cudaGetSymbolAddress(&p, g_out0); out0 = (float*)p;
    cudaGetSymbolAddress(&p, g_out1); out1 = (float*)p;
    cudaGetSymbolAddress(&p, g_a_se); a_se = (float*)p;
    cudaGetSymbolAddress(&p, g_a_de); a_de = (float*)p;
    cudaGetSymbolAddress(&p, g_a_so); a_so = (float*)p;
    cudaGetSymbolAddress(&p, g_a_do); a_do = (float*)p;
    cudaGetSymbolAddress(&p, g_amax); amax = (unsigned*)p;
    cudaGetSymbolAddress(&p, g_denom); denom = (float*)p;
    cudaGetSymbolAddress(&p, g_ebuf); ebuf = (float*)p;
    cudaGetSymbolAddress(&p, g_ksum); ksum = (float*)p;
    cudaGetSymbolAddress(&p, g_musum); musum = (float*)p;

    cudaFuncSetAttribute(gemm_tc<0>, cudaFuncAttributeMaxDynamicSharedMemorySize, SMEM_BYTES);
    cudaFuncSetAttribute(gemm_tc<1>, cudaFuncAttributeMaxDynamicSharedMemorySize, SMEM_BYTES);

    const long ND = (long)NN * DD;
    dim3 tcgrid(DD / GBN, (NN + GBM - 1) / GBM);   // (4, 782)

    // 1. projections (tensor cores, tf32, cp.async pipelined)
    gemm_tc<0><<<tcgrid, 256, SMEM_BYTES>>>(x_o, powm, pob, h_o, NN, nullptr);
    gemm_tc<0><<<tcgrid, 256, SMEM_BYTES>>>(x_e, pewm, peb, h_e, NN, nullptr);

    // 2. zero accumulators
    zero_buf<<<4096, 256>>>(out0, ND);
    zero_buf<<<4096, 256>>>(out1, ND);
    zero_buf<<<4, 256>>>(ksum, 2 * DD);
    zero_buf<<<4, 256>>>(musum, 2 * DD);

    int ah_blocks = (NN * 32 + 255) / 256;
    int eh_blocks = (EE * HH + 255) / 256;
    int sc_blocks = (EE * 32 + 255) / 256;
    int ie_blocks = (NN * HH + 255) / 256;

    // 3. attention dots (h_o read once for 3 vectors, h_e once for 1)
    compute_ah3<<<ah_blocks, 256>>>(h_o, a_d_e2o, a_de, a_s_o2o, a_so, a_d_o2o, a_do, NN);
    compute_ah3<<<ah_blocks, 256>>>(h_e, a_s_e2o, a_se, nullptr, nullptr, nullptr, nullptr, NN);

    // 4. metapath 0: entity -> openie
    init_edge_state<<<ie_blocks, 256>>>(amax, denom, NN * HH);
    edge_alpha_max<<<eh_blocks, 256>>>(e2o, e2o + EE, a_se, a_de, ebuf, amax, EE);
    edge_exp_sum<<<eh_blocks, 256>>>(e2o + EE, ebuf, amax, denom, EE);
    edge_scatter<<<sc_blocks, 256>>>(e2o, e2o + EE, h_e, ebuf, denom, out0, EE);

    // 5. metapath 1: openie -> openie
    init_edge_state<<<ie_blocks, 256>>>(amax, denom, NN * HH);
    edge_alpha_max<<<eh_blocks, 256>>>(o2o, o2o + EE, a_so, a_do, ebuf, amax, EE);
    edge_exp_sum<<<eh_blocks, 256>>>(o2o + EE, ebuf, amax, denom, EE);
    edge_scatter<<<sc_blocks, 256>>>(o2o, o2o + EE, h_o, ebuf, denom, out1, EE);

    // 6. column means of relu(out_m)
    mu_kernel<<<128, 512>>>(out0, musum, NN);
    mu_kernel<<<128, 512>>>(out1, musum + DD, NN);

    // 7. semantic-attention k vectors: sum_n tanh(relu(out_m) @ k_lin_w + b)
    gemm_tc<1><<<tcgrid, 256, SMEM_BYTES>>>(out0, klw, klb, nullptr, NN, ksum);
    gemm_tc<1><<<tcgrid, 256, SMEM_BYTES>>>(out1, klw, klb, nullptr, NN, ksum + DD);

    // 8. softmax over metapaths, pool, final linear
    final_kernel<<<1, 512>>>(qsem, linw, linb, out);
}

// round 6
// speedup vs baseline: 1.2450x; 1.2450x over previous
#include <cuda_runtime.h>
#include <cstdint>
#include <math.h>
#include <mma.h>

using namespace nvcuda;

#define NN 100000
#define EE 150000
#define DD 512
#define HH 8

#define GBM 128
#define GBN 128
#define GBK 32
#define APAD 8   // A row stride 40 floats
#define BPAD 8   // B row stride 136 floats

// ---------------- scratch ---------------------------------------------------
__device__ float g_h_o[(size_t)NN * DD];
__device__ float g_h_e[(size_t)NN * DD];
__device__ float g_out0[(size_t)NN * DD];
__device__ float g_out1[(size_t)NN * DD];
__device__ float g_a_se[NN * HH];
__device__ float g_a_de[NN * HH];
__device__ float g_a_so[NN * HH];
__device__ float g_a_do[NN * HH];
__device__ unsigned g_amax[NN * HH];
__device__ float g_denom[NN * HH];
__device__ float g_ebuf[EE * HH];
__device__ float g_ksum[2 * DD];
__device__ float g_musum[2 * DD];

// ---------------- helpers ---------------------------------------------------
__device__ __forceinline__ unsigned mapf(float f) {
    unsigned u = __float_as_uint(f);
    return (u & 0x80000000u) ? ~u : (u | 0x80000000u);
}
__device__ __forceinline__ float unmapf(unsigned u) {
    return __uint_as_float((u & 0x80000000u) ? (u & 0x7FFFFFFFu) : ~u);
}

__global__ void zero_buf(float* p, long n) {
    long i = (long)blockIdx.x * blockDim.x + threadIdx.x;
    long stride = (long)gridDim.x * blockDim.x;
    for (; i < n; i += stride) p[i] = 0.0f;
}

__global__ void init_edge_state(unsigned* amax, float* denom, int n) {
    int i = blockIdx.x * blockDim.x + threadIdx.x;
    if (i < n) { amax[i] = 0x007FFFFFu; denom[i] = 0.0f; }  // mapf(-inf)
}

// ---------------- TF32 TC GEMM, register-prefetch pipeline ------------------
// MODE 0: C = A@W + bias (stored).
// MODE 1: relu(A) applied at STS; epilogue accumulates sum_rows tanh(acc+bias)
//         into ksum_out (C not written).
template <int MODE>
__global__ void __launch_bounds__(256, 2) gemm_tc(
        const float* __restrict__ A, const float* __restrict__ W,
        const float* __restrict__ bias, float* __restrict__ C, int M,
        float* __restrict__ ksum_out) {
    __shared__ float As[GBM][GBK + APAD];      // 128 x 40
    __shared__ float Bs[GBK][GBN + BPAD];      // 32 x 136
    __shared__ float stage[8][16][20];
    __shared__ float ksred[GBN];

    int tid = threadIdx.x;
    int wid = tid >> 5;
    int lane = tid & 31;
    int warp_m = wid & 3;
    int warp_n = wid >> 2;
    int m0 = blockIdx.y * GBM;
    int n0 = blockIdx.x * GBN;
    int wm0 = warp_m * 32;
    int wn0 = warp_n * 64;

    if (MODE == 1 && tid < GBN) ksred[tid] = 0.0f;

    // per-thread load coordinates (4 x 16B per tile per thread)
    int a_row[4], a_c4[4], b_row[4], b_c4[4];
#pragma unroll
    for (int it = 0; it < 4; it++) {
        int idx = tid + it * 256;
        a_row[it] = idx >> 3;  a_c4[it] = (idx & 7) << 2;
        b_row[it] = idx >> 5;  b_c4[it] = (idx & 31) << 2;
    }

    float4 aReg[4], bReg[4];
    auto ldg_tile = [&](int k0) {
#pragma unroll
        for (int it = 0; it < 4; it++) {
            int gm = m0 + a_row[it];
            if (gm < M) aReg[it] = *(const float4*)(A + (size_t)gm * DD + k0 + a_c4[it]);
            else        aReg[it] = make_float4(0.f, 0.f, 0.f, 0.f);
            bReg[it] = *(const float4*)(W + (size_t)(k0 + b_row[it]) * DD + n0 + b_c4[it]);
        }
    };

    wmma::fragment<wmma::accumulator, 16, 16, 8, float> acc[2][4];
#pragma unroll
    for (int i = 0; i < 2; i++)
#pragma unroll
        for (int j = 0; j < 4; j++) wmma::fill_fragment(acc[i][j], 0.0f);

    ldg_tile(0);

    for (int k0 = 0; k0 < DD; k0 += GBK) {
        // commit prefetched tile to smem
#pragma unroll
        for (int it = 0; it < 4; it++) {
            float4 v = aReg[it];
            if (MODE == 1) {
                v.x = fmaxf(v.x, 0.f); v.y = fmaxf(v.y, 0.f);
                v.z = fmaxf(v.z, 0.f); v.w = fmaxf(v.w, 0.f);
            }
            *(float4*)(&As[a_row[it]][a_c4[it]]) = v;
            *(float4*)(&Bs[b_row[it]][b_c4[it]]) = bReg[it];
        }
        __syncthreads();

        // issue next tile's global loads; latency overlaps the MMA block below
        if (k0 + GBK < DD) ldg_tile(k0 + GBK);

#pragma unroll
        for (int kk = 0; kk < GBK; kk += 8) {
            wmma::fragment<wmma::matrix_a, 16, 16, 8, wmma::precision::tf32,
                           wmma::row_major> af[2];
            wmma::fragment<wmma::matrix_b, 16, 16, 8, wmma::precision::tf32,
                           wmma::row_major> bf[4];
#pragma unroll
            for (int i = 0; i < 2; i++) {
                wmma::load_matrix_sync(af[i], &As[wm0 + i * 16][kk], GBK + APAD);
#pragma unroll
                for (int t = 0; t < af[i].num_elements; t++)
                    af[i].x[t] = wmma::__float_to_tf32(af[i].x[t]);
            }
#pragma unroll
            for (int j = 0; j < 4; j++) {
                wmma::load_matrix_sync(bf[j], &Bs[kk][wn0 + j * 16], GBN + BPAD);
#pragma unroll
                for (int t = 0; t < bf[j].num_elements; t++)
                    bf[j].x[t] = wmma::__float_to_tf32(bf[j].x[t]);
            }
#pragma unroll
            for (int i = 0; i < 2; i++)
#pragma unroll
                for (int j = 0; j < 4; j++)
                    wmma::mma_sync(acc[i][j], af[i], bf[j], acc[i][j]);
        }
        __syncthreads();
    }

    // ---------------- epilogue ----------------
    int r = lane >> 1;
    int cbase = (lane & 1) * 8;
#pragma unroll
    for (int i = 0; i < 2; i++) {
#pragma unroll
        for (int j = 0; j < 4; j++) {
            wmma::store_matrix_sync(&stage[wid][0][0], acc[i][j], 20,
                                    wmma::mem_row_major);
            __syncwarp();
            int grow = m0 + wm0 + i * 16 + r;
            int gcol = n0 + wn0 + j * 16 + cbase;
            if (grow < M) {
                float4 v1 = *(const float4*)(&stage[wid][r][cbase]);
                float4 v2 = *(const float4*)(&stage[wid][r][cbase + 4]);
                float4 b1 = *(const float4*)(bias + gcol);
                float4 b2 = *(const float4*)(bias + gcol + 4);
                v1.x += b1.x; v1.y += b1.y; v1.z += b1.z; v1.w += b1.w;
                v2.x += b2.x; v2.y += b2.y; v2.z += b2.z; v2.w += b2.w;
                if (MODE == 0) {
                    *(float4*)(C + (size_t)grow * DD + gcol) = v1;
                    *(float4*)(C + (size_t)grow * DD + gcol + 4) = v2;
                } else {
                    int lc = wn0 + j * 16 + cbase;
                    atomicAdd(&ksred[lc + 0], tanhf(v1.x));
                    atomicAdd(&ksred[lc + 1], tanhf(v1.y));
                    atomicAdd(&ksred[lc + 2], tanhf(v1.z));
                    atomicAdd(&ksred[lc + 3], tanhf(v1.w));
                    atomicAdd(&ksred[lc + 4], tanhf(v2.x));
                    atomicAdd(&ksred[lc + 5], tanhf(v2.y));
                    atomicAdd(&ksred[lc + 6], tanhf(v2.z));
                    atomicAdd(&ksred[lc + 7], tanhf(v2.w));
                }
            }
            __syncwarp();
        }
    }
    if (MODE == 1) {
        __syncthreads();
        if (tid < GBN) atomicAdd(&ksum_out[n0 + tid], ksred[tid]);
    }
}

// ---------------- attention dots: 1 read of h, up to 3 att pairs ------------
__global__ void compute_ah3(const float* __restrict__ hmat,
                            const float* __restrict__ att0, float* __restrict__ a0,
                            const float* __restrict__ att1, float* __restrict__ a1,
                            const float* __restrict__ att2, float* __restrict__ a2,
                            int n_nodes) {
    int gt = blockIdx.x * blockDim.x + threadIdx.x;
    int warp = gt >> 5;
    int lane = threadIdx.x & 31;
    if (warp >= n_nodes) return;
    int base = lane * 16;
    const float4* hp = (const float4*)(hmat + (size_t)warp * DD + base);
    const float4* ap0 = (const float4*)(att0 + base);
    const float4* ap1 = att1 ? (const float4*)(att1 + base) : nullptr;
    const float4* ap2 = att2 ? (const float4*)(att2 + base) : nullptr;
    float s0 = 0.f, s1 = 0.f, s2 = 0.f;
#pragma unroll
    for (int q = 0; q < 4; q++) {
        float4 hv = hp[q];
        float4 av = ap0[q];
        s0 += hv.x * av.x + hv.y * av.y + hv.z * av.z + hv.w * av.w;
        if (ap1) {
            float4 bv = ap1[q];
            s1 += hv.x * bv.x + hv.y * bv.y + hv.z * bv.z + hv.w * bv.w;
        }
        if (ap2) {
            float4 cv = ap2[q];
            s2 += hv.x * cv.x + hv.y * cv.y + hv.z * cv.z + hv.w * cv.w;
        }
    }
#pragma unroll
    for (int d = 1; d <= 2; d <<= 1) {
        s0 += __shfl_xor_sync(0xffffffffu, s0, d);
        s1 += __shfl_xor_sync(0xffffffffu, s1, d);
        s2 += __shfl_xor_sync(0xffffffffu, s2, d);
    }
    if ((lane & 3) == 0) {
        int o = warp * HH + (lane >> 2);
        a0[o] = s0;
        if (a1) a1[o] = s1;
        if (a2) a2[o] = s2;
    }
}

// ---------------- edge pass 1: alpha + segment max --------------------------
__global__ void edge_alpha_max(const int* __restrict__ src,
                               const int* __restrict__ dst,
                               const float* __restrict__ asrc,
                               const float* __restrict__ adst,
                               float* __restrict__ alpha,
                               unsigned* __restrict__ amax, int ne) {
    int i = blockIdx.x * blockDim.x + threadIdx.x;
    if (i >= ne * HH) return;
    int e = i >> 3, h = i & 7;
    float v = asrc[src[e] * HH + h] + adst[dst[e] * HH + h];
    v = (v > 0.f) ? v : 0.2f * v;
    alpha[i] = v;
    atomicMax(&amax[dst[e] * HH + h], mapf(v));
}

// ---------------- edge pass 2: exp + segment sum ----------------------------
__global__ void edge_exp_sum(const int* __restrict__ dst,
                             float* __restrict__ alpha,
                             const unsigned* __restrict__ amax,
                             float* __restrict__ denom, int ne) {
    int i = blockIdx.x * blockDim.x + threadIdx.x;
    if (i >= ne * HH) return;
    int e = i >> 3, h = i & 7;
    float ex = expf(alpha[i] - unmapf(amax[dst[e] * HH + h]));
    alpha[i] = ex;
    atomicAdd(&denom[dst[e] * HH + h], ex);
}

// ---------------- edge pass 3: weighted scatter (vector red) ----------------
__global__ void edge_scatter(const int* __restrict__ src,
                             const int* __restrict__ dst,
                             const float* __restrict__ hsrc,
                             const float* __restrict__ exbuf,
                             const float* __restrict__ denom,
                             float* __restrict__ outb, int ne) {
    int gt = blockIdx.x * blockDim.x + threadIdx.x;
    int e = gt >> 5;
    int lane = threadIdx.x & 31;
    if (e >= ne) return;
    int s = src[e], d = dst[e];
    int h = lane >> 2;
    float w = exbuf[e * HH + h] / (denom[d * HH + h] + 1e-16f);
    const float4* hp = (const float4*)(hsrc + (size_t)s * DD + lane * 16);
    float* op = outb + (size_t)d * DD + lane * 16;
#pragma unroll
    for (int q = 0; q < 4; q++) {
        float4 v = hp[q];
        asm volatile("red.global.add.v4.f32 [%0], {%1, %2, %3, %4};"
                     :: "l"(op + q * 4), "f"(v.x * w), "f"(v.y * w),
                        "f"(v.z * w), "f"(v.w * w)
                     : "memory");
    }
}

// ---------------- column means of relu(out) ---------------------------------
__global__ void mu_kernel(const float* __restrict__ outb,
                          float* __restrict__ musum, int M) {
    int f = threadIdx.x;
    int chunk = (M + gridDim.x - 1) / gridDim.x;
    int r0 = blockIdx.x * chunk;
    int r1 = min(M, r0 + chunk);
    float acc = 0.f;
    for (int r = r0; r < r1; r++)
        acc += fmaxf(outb[(size_t)r * DD + f], 0.f);
    atomicAdd(&musum[f], acc);
}

// ---------------- final semantic attention + pool + linear ------------------
__global__ void final_kernel(const float* __restrict__ qsem,
                             const float* __restrict__ linw,
                             const float* __restrict__ linb,
                             float* __restrict__ out) {
    __shared__ float sh[DD];
    __shared__ float sv[2];
    int f = threadIdx.x;
    const float invN = 1.0f / (float)NN;
    float q = qsem[f];
    float v0 = g_ksum[f] * invN * q;
    float v1 = g_ksum[DD + f] * invN * q;

    sh[f] = v0; __syncthreads();
    for (int s = 256; s > 0; s >>= 1) { if (f < s) sh[f] += sh[f + s]; __syncthreads(); }
    if (f == 0) sv[0] = sh[0];
    __syncthreads();
    sh[f] = v1; __syncthreads();
    for (int s = 256; s > 0; s >>= 1) { if (f < s) sh[f] += sh[f + s]; __syncthreads(); }
    if (f == 0) sv[1] = sh[0];
    __syncthreads();

    float s0 = sv[0], s1 = sv[1];
    float mx = fmaxf(s0, s1);
    float e0 = expf(s0 - mx), e1 = expf(s1 - mx);
    float sem0 = e0 / (e0 + e1), sem1 = e1 / (e0 + e1);

    float pooled = (sem0 * g_musum[f] + sem1 * g_musum[DD + f]) * invN;
    float w0 = pooled * linw[f * 2 + 0];
    float w1 = pooled * linw[f * 2 + 1];

    sh[f] = w0; __syncthreads();
    for (int s = 256; s > 0; s >>= 1) { if (f < s) sh[f] += sh[f + s]; __syncthreads(); }
    if (f == 0) out[0] = sh[0] + linb[0];
    __syncthreads();
    sh[f] = w1; __syncthreads();
    for (int s = 256; s > 0; s >>= 1) { if (f < s) sh[f] += sh[f + s]; __syncthreads(); }
    if (f == 0) out[1] = sh[0] + linb[1];
}

// ---------------- host launcher ---------------------------------------------
extern "C" void kernel_launch(void* const* d_in, const int* in_sizes, int n_in,
                              void* d_out, int out_size) {
    const float* x_o  = (const float*)d_in[0];
    const float* x_e  = (const float*)d_in[1];
    const int*   e2o  = (const int*)d_in[2];
    const int*   o2o  = (const int*)d_in[3];
    const float* powm = (const float*)d_in[4];
    const float* pob  = (const float*)d_in[5];
    const float* pewm = (const float*)d_in[6];
    const float* peb  = (const float*)d_in[7];
    const float* a_s_e2o = (const float*)d_in[8];
    const float* a_d_e2o = (const float*)d_in[9];
    const float* a_s_o2o = (const float*)d_in[10];
    const float* a_d_o2o = (const float*)d_in[11];
    const float* klw  = (const float*)d_in[12];
    const float* klb  = (const float*)d_in[13];
    const float* qsem = (const float*)d_in[14];
    const float* linw = (const float*)d_in[15];
    const float* linb = (const float*)d_in[16];
    float* out = (float*)d_out;

    void* p;
    float *h_o, *h_e, *out0, *out1, *a_se, *a_de, *a_so, *a_do, *denom, *ebuf, *ksum, *musum;
    unsigned* amax;
    cudaGetSymbolAddress(&p, g_h_o);  h_o  = (float*)p;
    cudaGetSymbolAddress(&p, g_h_e);  h_e  = (float*)p;
    cudaGetSymbolAddress(&p, g_out0); out0 = (float*)p;
    cudaGetSymbolAddress(&p, g_out1); out1 = (float*)p;
    cudaGetSymbolAddress(&p, g_a_se); a_se = (float*)p;
    cudaGetSymbolAddress(&p, g_a_de); a_de = (float*)p;
    cudaGetSymbolAddress(&p, g_a_so); a_so = (float*)p;
    cudaGetSymbolAddress(&p, g_a_do); a_do = (float*)p;
    cudaGetSymbolAddress(&p, g_amax); amax = (unsigned*)p;
    cudaGetSymbolAddress(&p, g_denom); denom = (float*)p;
    cudaGetSymbolAddress(&p, g_ebuf); ebuf = (float*)p;
    cudaGetSymbolAddress(&p, g_ksum); ksum = (float*)p;
    cudaGetSymbolAddress(&p, g_musum); musum = (float*)p;

    const long ND = (long)NN * DD;
    dim3 tcgrid(DD / GBN, (NN + GBM - 1) / GBM);   // (4, 782)

    // 1. zero accumulators FIRST (launches 1-4; puts a GEMM at launch #6 for ncu)
    zero_buf<<<4096, 256>>>(out0, ND);
    zero_buf<<<4096, 256>>>(out1, ND);
    zero_buf<<<4, 256>>>(ksum, 2 * DD);
    zero_buf<<<4, 256>>>(musum, 2 * DD);

    // 2. projections (launches 5 and 6 — ncu -s 5 -c 1 captures gemm_tc<0> on x_e)
    gemm_tc<0><<<tcgrid, 256>>>(x_o, powm, pob, h_o, NN, nullptr);
    gemm_tc<0><<<tcgrid, 256>>>(x_e, pewm, peb, h_e, NN, nullptr);

    int ah_blocks = (NN * 32 + 255) / 256;
    int eh_blocks = (EE * HH + 255) / 256;
    int sc_blocks = (EE * 32 + 255) / 256;
    int ie_blocks = (NN * HH + 255) / 256;

    // 3. attention dots (h_o read once for 3 vectors, h_e once for 1)
    compute_ah3<<<ah_blocks, 256>>>(h_o, a_d_e2o, a_de, a_s_o2o, a_so, a_d_o2o, a_do, NN);
    compute_ah3<<<ah_blocks, 256>>>(h_e, a_s_e2o, a_se, nullptr, nullptr, nullptr, nullptr, NN);

    // 4. metapath 0: entity -> openie
    init_edge_state<<<ie_blocks, 256>>>(amax, denom, NN * HH);
    edge_alpha_max<<<eh_blocks, 256>>>(e2o, e2o + EE, a_se, a_de, ebuf, amax, EE);
    edge_exp_sum<<<eh_blocks, 256>>>(e2o + EE, ebuf, amax, denom, EE);
    edge_scatter<<<sc_blocks, 256>>>(e2o, e2o + EE, h_e, ebuf, denom, out0, EE);

    // 5. metapath 1: openie -> openie
    init_edge_state<<<ie_blocks, 256>>>(amax, denom, NN * HH);
    edge_alpha_max<<<eh_blocks, 256>>>(o2o, o2o + EE, a_so, a_do, ebuf, amax, EE);
    edge_exp_sum<<<eh_blocks, 256>>>(o2o + EE, ebuf, amax, denom, EE);
    edge_scatter<<<sc_blocks, 256>>>(o2o, o2o + EE, h_o, ebuf, denom, out1, EE);

    // 6. column means of relu(out_m)
    mu_kernel<<<128, 512>>>(out0, musum, NN);
    mu_kernel<<<128, 512>>>(out1, musum + DD, NN);

    // 7. semantic-attention k vectors: sum_n tanh(relu(out_m) @ k_lin_w + b)
    gemm_tc<1><<<tcgrid, 256>>>(out0, klw, klb, nullptr, NN, ksum);
    gemm_tc<1><<<tcgrid, 256>>>(out1, klw, klb, nullptr, NN, ksum + DD);

    // 8. softmax over metapaths, pool, final linear
    final_kernel<<<1, 512>>>(qsem, linw, linb, out);
}

// round 7
// speedup vs baseline: 1.7919x; 1.4392x over previous
#include <cuda_runtime.h>
#include <cuda_bf16.h>
#include <cstdint>
#include <math.h>
#include <mma.h>

using namespace nvcuda;

#define NN 100000
#define EE 150000
#define DD 512
#define HH 8

#define GBM 128
#define GBN 128
#define GBK 32
#define APADE 16   // As row stride 48 bf16 (96B)
#define BPADE 16   // Bs row stride 144 bf16 (288B)

// ---------------- scratch ---------------------------------------------------
__device__ float g_h_o[(size_t)NN * DD];
__device__ float g_h_e[(size_t)NN * DD];
__device__ float g_out0[(size_t)NN * DD];
__device__ float g_out1[(size_t)NN * DD];
__device__ float g_a_se[NN * HH];
__device__ float g_a_de[NN * HH];
__device__ float g_a_so[NN * HH];
__device__ float g_a_do[NN * HH];
__device__ unsigned g_amax[NN * HH];
__device__ float g_denom[NN * HH];
__device__ float g_ebuf[EE * HH];
__device__ float g_ksum[2 * DD];
__device__ float g_musum[2 * DD];

// ---------------- helpers ---------------------------------------------------
__device__ __forceinline__ unsigned mapf(float f) {
    unsigned u = __float_as_uint(f);
    return (u & 0x80000000u) ? ~u : (u | 0x80000000u);
}
__device__ __forceinline__ float unmapf(unsigned u) {
    return __uint_as_float((u & 0x80000000u) ? (u & 0x7FFFFFFFu) : ~u);
}

__global__ void zero_buf(float* p, long n) {
    long i = (long)blockIdx.x * blockDim.x + threadIdx.x;
    long stride = (long)gridDim.x * blockDim.x;
    for (; i < n; i += stride) p[i] = 0.0f;
}

__global__ void init_edge_state(unsigned* amax, float* denom, int n) {
    int i = blockIdx.x * blockDim.x + threadIdx.x;
    if (i < n) { amax[i] = 0x007FFFFFu; denom[i] = 0.0f; }  // mapf(-inf)
}

// ---------------- BF16 TC GEMM (R3 loop structure, bf16 tiles) --------------
// MODE 0: C = A@W + bias (stored, fp32).
// MODE 1: relu(A) applied before bf16 convert at STS; epilogue accumulates
//         sum_rows tanh(acc+bias) into ksum_out (C not written).
template <int MODE>
__global__ void __launch_bounds__(256) gemm_tc(
        const float* __restrict__ A, const float* __restrict__ W,
        const float* __restrict__ bias, float* __restrict__ C, int M,
        float* __restrict__ ksum_out) {
    __shared__ __nv_bfloat16 As[GBM][GBK + APADE];   // 128 x 48
    __shared__ __nv_bfloat16 Bs[GBK][GBN + BPADE];   // 32 x 144
    __shared__ float stage[8][16][20];
    __shared__ float ksred[GBN];

    int tid = threadIdx.x;
    int wid = tid >> 5;
    int lane = tid & 31;
    int warp_m = wid & 3;
    int warp_n = wid >> 2;
    int m0 = blockIdx.y * GBM;
    int n0 = blockIdx.x * GBN;
    int wm0 = warp_m * 32;
    int wn0 = warp_n * 64;

    if (MODE == 1 && tid < GBN) ksred[tid] = 0.0f;

    wmma::fragment<wmma::accumulator, 16, 16, 16, float> acc[2][4];
#pragma unroll
    for (int i = 0; i < 2; i++)
#pragma unroll
        for (int j = 0; j < 4; j++) wmma::fill_fragment(acc[i][j], 0.0f);

    for (int k0 = 0; k0 < DD; k0 += GBK) {
        // A tile: 128x32 fp32 -> bf16 (4 x float4 per thread)
#pragma unroll
        for (int it = 0; it < 4; it++) {
            int idx = tid + it * 256;
            int row = idx >> 3;
            int c4 = (idx & 7) << 2;
            int gm = m0 + row;
            float4 v = make_float4(0.f, 0.f, 0.f, 0.f);
            if (gm < M) v = *(const float4*)(A + (size_t)gm * DD + k0 + c4);
            if (MODE == 1) {
                v.x = fmaxf(v.x, 0.f); v.y = fmaxf(v.y, 0.f);
                v.z = fmaxf(v.z, 0.f); v.w = fmaxf(v.w, 0.f);
            }
            *(__nv_bfloat162*)(&As[row][c4])     = __floats2bfloat162_rn(v.x, v.y);
            *(__nv_bfloat162*)(&As[row][c4 + 2]) = __floats2bfloat162_rn(v.z, v.w);
        }
        // B tile: 32x128 fp32 -> bf16
#pragma unroll
        for (int it = 0; it < 4; it++) {
            int idx = tid + it * 256;
            int row = idx >> 5;
            int c4 = (idx & 31) << 2;
            float4 v = *(const float4*)(W + (size_t)(k0 + row) * DD + n0 + c4);
            *(__nv_bfloat162*)(&Bs[row][c4])     = __floats2bfloat162_rn(v.x, v.y);
            *(__nv_bfloat162*)(&Bs[row][c4 + 2]) = __floats2bfloat162_rn(v.z, v.w);
        }
        __syncthreads();

#pragma unroll
        for (int kk = 0; kk < GBK; kk += 16) {
            wmma::fragment<wmma::matrix_a, 16, 16, 16, __nv_bfloat16,
                           wmma::row_major> af[2];
            wmma::fragment<wmma::matrix_b, 16, 16, 16, __nv_bfloat16,
                           wmma::row_major> bf[4];
#pragma unroll
            for (int i = 0; i < 2; i++)
                wmma::load_matrix_sync(af[i], &As[wm0 + i * 16][kk], GBK + APADE);
#pragma unroll
            for (int j = 0; j < 4; j++)
                wmma::load_matrix_sync(bf[j], &Bs[kk][wn0 + j * 16], GBN + BPADE);
#pragma unroll
            for (int i = 0; i < 2; i++)
#pragma unroll
                for (int j = 0; j < 4; j++)
                    wmma::mma_sync(acc[i][j], af[i], bf[j], acc[i][j]);
        }
        __syncthreads();
    }

    // ---------------- epilogue ----------------
    int r = lane >> 1;
    int cbase = (lane & 1) * 8;
#pragma unroll
    for (int i = 0; i < 2; i++) {
#pragma unroll
        for (int j = 0; j < 4; j++) {
            wmma::store_matrix_sync(&stage[wid][0][0], acc[i][j], 20,
                                    wmma::mem_row_major);
            __syncwarp();
            int grow = m0 + wm0 + i * 16 + r;
            int gcol = n0 + wn0 + j * 16 + cbase;
            if (grow < M) {
                float4 v1 = *(const float4*)(&stage[wid][r][cbase]);
                float4 v2 = *(const float4*)(&stage[wid][r][cbase + 4]);
                float4 b1 = *(const float4*)(bias + gcol);
                float4 b2 = *(const float4*)(bias + gcol + 4);
                v1.x += b1.x; v1.y += b1.y; v1.z += b1.z; v1.w += b1.w;
                v2.x += b2.x; v2.y += b2.y; v2.z += b2.z; v2.w += b2.w;
                if (MODE == 0) {
                    *(float4*)(C + (size_t)grow * DD + gcol) = v1;
                    *(float4*)(C + (size_t)grow * DD + gcol + 4) = v2;
                } else {
                    int lc = wn0 + j * 16 + cbase;
                    atomicAdd(&ksred[lc + 0], tanhf(v1.x));
                    atomicAdd(&ksred[lc + 1], tanhf(v1.y));
                    atomicAdd(&ksred[lc + 2], tanhf(v1.z));
                    atomicAdd(&ksred[lc + 3], tanhf(v1.w));
                    atomicAdd(&ksred[lc + 4], tanhf(v2.x));
                    atomicAdd(&ksred[lc + 5], tanhf(v2.y));
                    atomicAdd(&ksred[lc + 6], tanhf(v2.z));
                    atomicAdd(&ksred[lc + 7], tanhf(v2.w));
                }
            }
            __syncwarp();
        }
    }
    if (MODE == 1) {
        __syncthreads();
        if (tid < GBN) atomicAdd(&ksum_out[n0 + tid], ksred[tid]);
    }
}

// ---------------- attention dots: 1 read of h, up to 3 att pairs ------------
__global__ void compute_ah3(const float* __restrict__ hmat,
                            const float* __restrict__ att0, float* __restrict__ a0,
                            const float* __restrict__ att1, float* __restrict__ a1,
                            const float* __restrict__ att2, float* __restrict__ a2,
                            int n_nodes) {
    int gt = blockIdx.x * blockDim.x + threadIdx.x;
    int warp = gt >> 5;
    int lane = threadIdx.x & 31;
    if (warp >= n_nodes) return;
    int base = lane * 16;
    const float4* hp = (const float4*)(hmat + (size_t)warp * DD + base);
    const float4* ap0 = (const float4*)(att0 + base);
    const float4* ap1 = att1 ? (const float4*)(att1 + base) : nullptr;
    const float4* ap2 = att2 ? (const float4*)(att2 + base) : nullptr;
    float s0 = 0.f, s1 = 0.f, s2 = 0.f;
#pragma unroll
    for (int q = 0; q < 4; q++) {
        float4 hv = hp[q];
        float4 av = ap0[q];
        s0 += hv.x * av.x + hv.y * av.y + hv.z * av.z + hv.w * av.w;
        if (ap1) {
            float4 bv = ap1[q];
            s1 += hv.x * bv.x + hv.y * bv.y + hv.z * bv.z + hv.w * bv.w;
        }
        if (ap2) {
            float4 cv = ap2[q];
            s2 += hv.x * cv.x + hv.y * cv.y + hv.z * cv.z + hv.w * cv.w;
        }
    }
#pragma unroll
    for (int d = 1; d <= 2; d <<= 1) {
        s0 += __shfl_xor_sync(0xffffffffu, s0, d);
        s1 += __shfl_xor_sync(0xffffffffu, s1, d);
        s2 += __shfl_xor_sync(0xffffffffu, s2, d);
    }
    if ((lane & 3) == 0) {
        int o = warp * HH + (lane >> 2);
        a0[o] = s0;
        if (a1) a1[o] = s1;
        if (a2) a2[o] = s2;
    }
}

// ---------------- edge pass 1: alpha + segment max --------------------------
__global__ void edge_alpha_max(const int* __restrict__ src,
                               const int* __restrict__ dst,
                               const float* __restrict__ asrc,
                               const float* __restrict__ adst,
                               float* __restrict__ alpha,
                               unsigned* __restrict__ amax, int ne) {
    int i = blockIdx.x * blockDim.x + threadIdx.x;
    if (i >= ne * HH) return;
    int e = i >> 3, h = i & 7;
    float v = asrc[src[e] * HH + h] + adst[dst[e] * HH + h];
    v = (v > 0.f) ? v : 0.2f * v;
    alpha[i] = v;
    atomicMax(&amax[dst[e] * HH + h], mapf(v));
}

// ---------------- edge pass 2: exp + segment sum ----------------------------
__global__ void edge_exp_sum(const int* __restrict__ dst,
                             float* __restrict__ alpha,
                             const unsigned* __restrict__ amax,
                             float* __restrict__ denom, int ne) {
    int i = blockIdx.x * blockDim.x + threadIdx.x;
    if (i >= ne * HH) return;
    int e = i >> 3, h = i & 7;
    float ex = expf(alpha[i] - unmapf(amax[dst[e] * HH + h]));
    alpha[i] = ex;
    atomicAdd(&denom[dst[e] * HH + h], ex);
}

// ---------------- edge pass 3: weighted scatter (vector red) ----------------
__global__ void edge_scatter(const int* __restrict__ src,
                             const int* __restrict__ dst,
                             const float* __restrict__ hsrc,
                             const float* __restrict__ exbuf,
                             const float* __restrict__ denom,
                             float* __restrict__ outb, int ne) {
    int gt = blockIdx.x * blockDim.x + threadIdx.x;
    int e = gt >> 5;
    int lane = threadIdx.x & 31;
    if (e >= ne) return;
    int s = src[e], d = dst[e];
    int h = lane >> 2;
    float w = exbuf[e * HH + h] / (denom[d * HH + h] + 1e-16f);
    const float4* hp = (const float4*)(hsrc + (size_t)s * DD + lane * 16);
    float* op = outb + (size_t)d * DD + lane * 16;
#pragma unroll
    for (int q = 0; q < 4; q++) {
        float4 v = hp[q];
        asm volatile("red.global.add.v4.f32 [%0], {%1, %2, %3, %4};"
                     :: "l"(op + q * 4), "f"(v.x * w), "f"(v.y * w),
                        "f"(v.z * w), "f"(v.w * w)
                     : "memory");
    }
}

// ---------------- column means of relu(out) ---------------------------------
__global__ void mu_kernel(const float* __restrict__ outb,
                          float* __restrict__ musum, int M) {
    int f = threadIdx.x;
    int chunk = (M + gridDim.x - 1) / gridDim.x;
    int r0 = blockIdx.x * chunk;
    int r1 = min(M, r0 + chunk);
    float acc = 0.f;
    for (int r = r0; r < r1; r++)
        acc += fmaxf(outb[(size_t)r * DD + f], 0.f);
    atomicAdd(&musum[f], acc);
}

// ---------------- final semantic attention + pool + linear ------------------
__global__ void final_kernel(const float* __restrict__ qsem,
                             const float* __restrict__ linw,
                             const float* __restrict__ linb,
                             float* __restrict__ out) {
    __shared__ float sh[DD];
    __shared__ float sv[2];
    int f = threadIdx.x;
    const float invN = 1.0f / (float)NN;
    float q = qsem[f];
    float v0 = g_ksum[f] * invN * q;
    float v1 = g_ksum[DD + f] * invN * q;

    sh[f] = v0; __syncthreads();
    for (int s = 256; s > 0; s >>= 1) { if (f < s) sh[f] += sh[f + s]; __syncthreads(); }
    if (f == 0) sv[0] = sh[0];
    __syncthreads();
    sh[f] = v1; __syncthreads();
    for (int s = 256; s > 0; s >>= 1) { if (f < s) sh[f] += sh[f + s]; __syncthreads(); }
    if (f == 0) sv[1] = sh[0];
    __syncthreads();

    float s0 = sv[0], s1 = sv[1];
    float mx = fmaxf(s0, s1);
    float e0 = expf(s0 - mx), e1 = expf(s1 - mx);
    float sem0 = e0 / (e0 + e1), sem1 = e1 / (e0 + e1);

    float pooled = (sem0 * g_musum[f] + sem1 * g_musum[DD + f]) * invN;
    float w0 = pooled * linw[f * 2 + 0];
    float w1 = pooled * linw[f * 2 + 1];

    sh[f] = w0; __syncthreads();
    for (int s = 256; s > 0; s >>= 1) { if (f < s) sh[f] += sh[f + s]; __syncthreads(); }
    if (f == 0) out[0] = sh[0] + linb[0];
    __syncthreads();
    sh[f] = w1; __syncthreads();
    for (int s = 256; s > 0; s >>= 1) { if (f < s) sh[f] += sh[f + s]; __syncthreads(); }
    if (f == 0) out[1] = sh[0] + linb[1];
}

// ---------------- host launcher ---------------------------------------------
extern "C" void kernel_launch(void* const* d_in, const int* in_sizes, int n_in,
                              void* d_out, int out_size) {
    const float* x_o  = (const float*)d_in[0];
    const float* x_e  = (const float*)d_in[1];
    const int*   e2o  = (const int*)d_in[2];
    const int*   o2o  = (const int*)d_in[3];
    const float* powm = (const float*)d_in[4];
    const float* pob  = (const float*)d_in[5];
    const float* pewm = (const float*)d_in[6];
    const float* peb  = (const float*)d_in[7];
    const float* a_s_e2o = (const float*)d_in[8];
    const float* a_d_e2o = (const float*)d_in[9];
    const float* a_s_o2o = (const float*)d_in[10];
    const float* a_d_o2o = (const float*)d_in[11];
    const float* klw  = (const float*)d_in[12];
    const float* klb  = (const float*)d_in[13];
    const float* qsem = (const float*)d_in[14];
    const float* linw = (const float*)d_in[15];
    const float* linb = (const float*)d_in[16];
    float* out = (float*)d_out;

    void* p;
    float *h_o, *h_e, *out0, *out1, *a_se, *a_de, *a_so, *a_do, *denom, *ebuf, *ksum, *musum;
    unsigned* amax;
    cudaGetSymbolAddress(&p, g_h_o);  h_o  = (float*)p;
    cudaGetSymbolAddress(&p, g_h_e);  h_e  = (float*)p;
    cudaGetSymbolAddress(&p, g_out0); out0 = (float*)p;
    cudaGetSymbolAddress(&p, g_out1); out1 = (float*)p;
    cudaGetSymbolAddress(&p, g_a_se); a_se = (float*)p;
    cudaGetSymbolAddress(&p, g_a_de); a_de = (float*)p;
    cudaGetSymbolAddress(&p, g_a_so); a_so = (float*)p;
    cudaGetSymbolAddress(&p, g_a_do); a_do = (float*)p;
    cudaGetSymbolAddress(&p, g_amax); amax = (unsigned*)p;
    cudaGetSymbolAddress(&p, g_denom); denom = (float*)p;
    cudaGetSymbolAddress(&p, g_ebuf); ebuf = (float*)p;
    cudaGetSymbolAddress(&p, g_ksum); ksum = (float*)p;
    cudaGetSymbolAddress(&p, g_musum); musum = (float*)p;

    const long ND = (long)NN * DD;
    dim3 tcgrid(DD / GBN, (NN + GBM - 1) / GBM);   // (4, 782)

    // 1. zero accumulators
    zero_buf<<<4096, 256>>>(out0, ND);
    zero_buf<<<4096, 256>>>(out1, ND);
    zero_buf<<<4, 256>>>(ksum, 2 * DD);
    zero_buf<<<4, 256>>>(musum, 2 * DD);

    // 2. projections (bf16 tensor cores)
    gemm_tc<0><<<tcgrid, 256>>>(x_o, powm, pob, h_o, NN, nullptr);
    gemm_tc<0><<<tcgrid, 256>>>(x_e, pewm, peb, h_e, NN, nullptr);

    int ah_blocks = (NN * 32 + 255) / 256;
    int eh_blocks = (EE * HH + 255) / 256;
    int sc_blocks = (EE * 32 + 255) / 256;
    int ie_blocks = (NN * HH + 255) / 256;

    // 3. attention dots
    compute_ah3<<<ah_blocks, 256>>>(h_o, a_d_e2o, a_de, a_s_o2o, a_so, a_d_o2o, a_do, NN);
    compute_ah3<<<ah_blocks, 256>>>(h_e, a_s_e2o, a_se, nullptr, nullptr, nullptr, nullptr, NN);

    // 4. metapath 0: entity -> openie
    init_edge_state<<<ie_blocks, 256>>>(amax, denom, NN * HH);
    edge_alpha_max<<<eh_blocks, 256>>>(e2o, e2o + EE, a_se, a_de, ebuf, amax, EE);
    edge_exp_sum<<<eh_blocks, 256>>>(e2o + EE, ebuf, amax, denom, EE);
    edge_scatter<<<sc_blocks, 256>>>(e2o, e2o + EE, h_e, ebuf, denom, out0, EE);

    // 5. metapath 1: openie -> openie
    init_edge_state<<<ie_blocks, 256>>>(amax, denom, NN * HH);
    edge_alpha_max<<<eh_blocks, 256>>>(o2o, o2o + EE, a_so, a_do, ebuf, amax, EE);
    edge_exp_sum<<<eh_blocks, 256>>>(o2o + EE, ebuf, amax, denom, EE);
    edge_scatter<<<sc_blocks, 256>>>(o2o, o2o + EE, h_o, ebuf, denom, out1, EE);

    // 6. column means of relu(out_m)
    mu_kernel<<<128, 512>>>(out0, musum, NN);
    mu_kernel<<<128, 512>>>(out1, musum + DD, NN);

    // 7. semantic-attention k vectors
    gemm_tc<1><<<tcgrid, 256>>>(out0, klw, klb, nullptr, NN, ksum);
    gemm_tc<1><<<tcgrid, 256>>>(out1, klw, klb, nullptr, NN, ksum + DD);

    // 8. softmax over metapaths, pool, final linear
    final_kernel<<<1, 512>>>(qsem, linw, linb, out);
}

// round 8
// speedup vs baseline: 1.9297x; 1.0769x over previous
#include <cuda_runtime.h>
#include <cuda_bf16.h>
#include <cstdint>
#include <math.h>
#include <mma.h>

using namespace nvcuda;

#define NN 100000
#define EE 150000
#define DD 512
#define HH 8

#define GBM 128
#define GBN 128
#define GBK 32
#define APADE 16   // As row stride 48 bf16 (96B)
#define BPADE 16   // Bs row stride 144 bf16 (288B)

// ---------------- scratch ---------------------------------------------------
__device__ float g_h_o[(size_t)NN * DD];
__device__ float g_h_e[(size_t)NN * DD];
__device__ float g_out0[(size_t)NN * DD];
__device__ float g_out1[(size_t)NN * DD];
__device__ __nv_bfloat16 g_Ab[(size_t)NN * DD];   // bf16 A operand (reused 4x)
__device__ __nv_bfloat16 g_Wb[DD * DD];           // bf16 W operand (reused 3x)
__device__ float g_a_se[NN * HH];
__device__ float g_a_de[NN * HH];
__device__ float g_a_so[NN * HH];
__device__ float g_a_do[NN * HH];
__device__ unsigned g_amax[NN * HH];
__device__ float g_denom[NN * HH];
__device__ float g_ebuf[EE * HH];
__device__ float g_ksum[2 * DD];
__device__ float g_musum[2 * DD];

// ---------------- helpers ---------------------------------------------------
__device__ __forceinline__ unsigned mapf(float f) {
    unsigned u = __float_as_uint(f);
    return (u & 0x80000000u) ? ~u : (u | 0x80000000u);
}
__device__ __forceinline__ float unmapf(unsigned u) {
    return __uint_as_float((u & 0x80000000u) ? (u & 0x7FFFFFFFu) : ~u);
}

__global__ void zero_buf(float* p, long n) {
    long i = (long)blockIdx.x * blockDim.x + threadIdx.x;
    long stride = (long)gridDim.x * blockDim.x;
    for (; i < n; i += stride) p[i] = 0.0f;
}

__global__ void init_edge_state(unsigned* amax, float* denom, int n) {
    int i = blockIdx.x * blockDim.x + threadIdx.x;
    if (i < n) { amax[i] = 0x007FFFFFu; denom[i] = 0.0f; }  // mapf(-inf)
}

// ---------------- fp32 -> bf16 conversion (vectorized) ----------------------
__global__ void conv_bf(const float* __restrict__ src,
                        __nv_bfloat16* __restrict__ dst, long n) {
    long i = ((long)blockIdx.x * blockDim.x + threadIdx.x) * 4;
    long stride = (long)gridDim.x * blockDim.x * 4;
    for (; i < n; i += stride) {
        float4 v = *(const float4*)(src + i);
        *(__nv_bfloat162*)(dst + i)     = __floats2bfloat162_rn(v.x, v.y);
        *(__nv_bfloat162*)(dst + i + 2) = __floats2bfloat162_rn(v.z, v.w);
    }
}

// ---------------- fused relu + bf16 convert + column sums -------------------
__global__ void convmu(const float* __restrict__ outb,
                       __nv_bfloat16* __restrict__ dst,
                       float* __restrict__ musum, int M) {
    int f = threadIdx.x;                   // 512 threads = columns
    int chunk = (M + gridDim.x - 1) / gridDim.x;
    int r0 = blockIdx.x * chunk;
    int r1 = min(M, r0 + chunk);
    float acc = 0.f;
    for (int r = r0; r < r1; r++) {
        float v = fmaxf(outb[(size_t)r * DD + f], 0.f);
        acc += v;
        dst[(size_t)r * DD + f] = __float2bfloat16(v);
    }
    atomicAdd(&musum[f], acc);
}

// ---------------- BF16 TC GEMM, 2-stage cp.async, static smem ---------------
// MODE 0: C = A@W + bias (stored fp32).
// MODE 1: epilogue accumulates sum_rows tanh(acc+bias) into ksum_out.
template <int MODE>
__global__ void __launch_bounds__(256) gemm_bf(
        const __nv_bfloat16* __restrict__ A, const __nv_bfloat16* __restrict__ W,
        const float* __restrict__ bias, float* __restrict__ C, int M,
        float* __restrict__ ksum_out) {
    __shared__ __nv_bfloat16 As[2][GBM][GBK + APADE];   // 2 x 128 x 48
    __shared__ __nv_bfloat16 Bs[2][GBK][GBN + BPADE];   // 2 x 32 x 144
    __shared__ float stage[8][16][20];
    __shared__ float ksred[GBN];

    int tid = threadIdx.x;
    int wid = tid >> 5;
    int lane = tid & 31;
    int warp_m = wid & 3;
    int warp_n = wid >> 2;
    int m0 = blockIdx.y * GBM;
    int n0 = blockIdx.x * GBN;
    int wm0 = warp_m * 32;
    int wn0 = warp_n * 64;

    if (MODE == 1 && tid < GBN) ksred[tid] = 0.0f;

    // A tile: 128x32 bf16 = 512 x 16B chunks; B tile: 32x128 bf16 = 512 chunks
    auto load_stage = [&](int s, int k0) {
#pragma unroll
        for (int it = 0; it < 2; it++) {
            int idx = tid + it * 256;
            int ar = idx >> 2, ac = (idx & 3) * 8;
            int gm = m0 + ar;
            const __nv_bfloat16* srcA =
                A + (size_t)(gm < M ? gm : M - 1) * DD + k0 + ac;
            uint32_t dstA = (uint32_t)__cvta_generic_to_shared(&As[s][ar][ac]);
            int szA = (gm < M) ? 16 : 0;
            asm volatile("cp.async.cg.shared.global [%0], [%1], 16, %2;"
                         :: "r"(dstA), "l"(srcA), "r"(szA));
            int br = idx >> 4, bc = (idx & 15) * 8;
            const __nv_bfloat16* srcB = W + (size_t)(k0 + br) * DD + n0 + bc;
            uint32_t dstB = (uint32_t)__cvta_generic_to_shared(&Bs[s][br][bc]);
            asm volatile("cp.async.cg.shared.global [%0], [%1], 16, 16;"
                         :: "r"(dstB), "l"(srcB));
        }
    };

    wmma::fragment<wmma::accumulator, 16, 16, 16, float> acc[2][4];
#pragma unroll
    for (int i = 0; i < 2; i++)
#pragma unroll
        for (int j = 0; j < 4; j++) wmma::fill_fragment(acc[i][j], 0.0f);

    load_stage(0, 0);
    asm volatile("cp.async.commit_group;");

    int sbuf = 0;
    for (int k0 = 0; k0 < DD; k0 += GBK) {
        if (k0 + GBK < DD) load_stage(sbuf ^ 1, k0 + GBK);
        asm volatile("cp.async.commit_group;");
        asm volatile("cp.async.wait_group 1;");
        __syncthreads();

#pragma unroll
        for (int kk = 0; kk < GBK; kk += 16) {
            wmma::fragment<wmma::matrix_a, 16, 16, 16, __nv_bfloat16,
                           wmma::row_major> af[2];
            wmma::fragment<wmma::matrix_b, 16, 16, 16, __nv_bfloat16,
                           wmma::row_major> bf[4];
#pragma unroll
            for (int i = 0; i < 2; i++)
                wmma::load_matrix_sync(af[i], &As[sbuf][wm0 + i * 16][kk],
                                       GBK + APADE);
#pragma unroll
            for (int j = 0; j < 4; j++)
                wmma::load_matrix_sync(bf[j], &Bs[sbuf][kk][wn0 + j * 16],
                                       GBN + BPADE);
#pragma unroll
            for (int i = 0; i < 2; i++)
#pragma unroll
                for (int j = 0; j < 4; j++)
                    wmma::mma_sync(acc[i][j], af[i], bf[j], acc[i][j]);
        }
        __syncthreads();
        sbuf ^= 1;
    }

    // ---------------- epilogue ----------------
    int r = lane >> 1;
    int cbase = (lane & 1) * 8;
#pragma unroll
    for (int i = 0; i < 2; i++) {
#pragma unroll
        for (int j = 0; j < 4; j++) {
            wmma::store_matrix_sync(&stage[wid][0][0], acc[i][j], 20,
                                    wmma::mem_row_major);
            __syncwarp();
            int grow = m0 + wm0 + i * 16 + r;
            int gcol = n0 + wn0 + j * 16 + cbase;
            if (grow < M) {
                float4 v1 = *(const float4*)(&stage[wid][r][cbase]);
                float4 v2 = *(const float4*)(&stage[wid][r][cbase + 4]);
                float4 b1 = *(const float4*)(bias + gcol);
                float4 b2 = *(const float4*)(bias + gcol + 4);
                v1.x += b1.x; v1.y += b1.y; v1.z += b1.z; v1.w += b1.w;
                v2.x += b2.x; v2.y += b2.y; v2.z += b2.z; v2.w += b2.w;
                if (MODE == 0) {
                    *(float4*)(C + (size_t)grow * DD + gcol) = v1;
                    *(float4*)(C + (size_t)grow * DD + gcol + 4) = v2;
                } else {
                    int lc = wn0 + j * 16 + cbase;
                    atomicAdd(&ksred[lc + 0], tanhf(v1.x));
                    atomicAdd(&ksred[lc + 1], tanhf(v1.y));
                    atomicAdd(&ksred[lc + 2], tanhf(v1.z));
                    atomicAdd(&ksred[lc + 3], tanhf(v1.w));
                    atomicAdd(&ksred[lc + 4], tanhf(v2.x));
                    atomicAdd(&ksred[lc + 5], tanhf(v2.y));
                    atomicAdd(&ksred[lc + 6], tanhf(v2.z));
                    atomicAdd(&ksred[lc + 7], tanhf(v2.w));
                }
            }
            __syncwarp();
        }
    }
    if (MODE == 1) {
        __syncthreads();
        if (tid < GBN) atomicAdd(&ksum_out[n0 + tid], ksred[tid]);
    }
}

// ---------------- attention dots: 1 read of h, up to 3 att pairs ------------
__global__ void compute_ah3(const float* __restrict__ hmat,
                            const float* __restrict__ att0, float* __restrict__ a0,
                            const float* __restrict__ att1, float* __restrict__ a1,
                            const float* __restrict__ att2, float* __restrict__ a2,
                            int n_nodes) {
    int gt = blockIdx.x * blockDim.x + threadIdx.x;
    int warp = gt >> 5;
    int lane = threadIdx.x & 31;
    if (warp >= n_nodes) return;
    int base = lane * 16;
    const float4* hp = (const float4*)(hmat + (size_t)warp * DD + base);
    const float4* ap0 = (const float4*)(att0 + base);
    const float4* ap1 = att1 ? (const float4*)(att1 + base) : nullptr;
    const float4* ap2 = att2 ? (const float4*)(att2 + base) : nullptr;
    float s0 = 0.f, s1 = 0.f, s2 = 0.f;
#pragma unroll
    for (int q = 0; q < 4; q++) {
        float4 hv = hp[q];
        float4 av = ap0[q];
        s0 += hv.x * av.x + hv.y * av.y + hv.z * av.z + hv.w * av.w;
        if (ap1) {
            float4 bv = ap1[q];
            s1 += hv.x * bv.x + hv.y * bv.y + hv.z * bv.z + hv.w * bv.w;
        }
        if (ap2) {
            float4 cv = ap2[q];
            s2 += hv.x * cv.x + hv.y * cv.y + hv.z * cv.z + hv.w * cv.w;
        }
    }
#pragma unroll
    for (int d = 1; d <= 2; d <<= 1) {
        s0 += __shfl_xor_sync(0xffffffffu, s0, d);
        s1 += __shfl_xor_sync(0xffffffffu, s1, d);
        s2 += __shfl_xor_sync(0xffffffffu, s2, d);
    }
    if ((lane & 3) == 0) {
        int o = warp * HH + (lane >> 2);
        a0[o] = s0;
        if (a1) a1[o] = s1;
        if (a2) a2[o] = s2;
    }
}

// ---------------- edge pass 1: alpha + segment max --------------------------
__global__ void edge_alpha_max(const int* __restrict__ src,
                               const int* __restrict__ dst,
                               const float* __restrict__ asrc,
                               const float* __restrict__ adst,
                               float* __restrict__ alpha,
                               unsigned* __restrict__ amax, int ne) {
    int i = blockIdx.x * blockDim.x + threadIdx.x;
    if (i >= ne * HH) return;
    int e = i >> 3, h = i & 7;
    float v = asrc[src[e] * HH + h] + adst[dst[e] * HH + h];
    v = (v > 0.f) ? v : 0.2f * v;
    alpha[i] = v;
    atomicMax(&amax[dst[e] * HH + h], mapf(v));
}

// ---------------- edge pass 2: exp + segment sum ----------------------------
__global__ void edge_exp_sum(const int* __restrict__ dst,
                             float* __restrict__ alpha,
                             const unsigned* __restrict__ amax,
                             float* __restrict__ denom, int ne) {
    int i = blockIdx.x * blockDim.x + threadIdx.x;
    if (i >= ne * HH) return;
    int e = i >> 3, h = i & 7;
    float ex = expf(alpha[i] - unmapf(amax[dst[e] * HH + h]));
    alpha[i] = ex;
    atomicAdd(&denom[dst[e] * HH + h], ex);
}

// ---------------- edge pass 3: weighted scatter (vector red) ----------------
__global__ void edge_scatter(const int* __restrict__ src,
                             const int* __restrict__ dst,
                             const float* __restrict__ hsrc,
                             const float* __restrict__ exbuf,
                             const float* __restrict__ denom,
                             float* __restrict__ outb, int ne) {
    int gt = blockIdx.x * blockDim.x + threadIdx.x;
    int e = gt >> 5;
    int lane = threadIdx.x & 31;
    if (e >= ne) return;
    int s = src[e], d = dst[e];
    int h = lane >> 2;
    float w = exbuf[e * HH + h] / (denom[d * HH + h] + 1e-16f);
    const float4* hp = (const float4*)(hsrc + (size_t)s * DD + lane * 16);
    float* op = outb + (size_t)d * DD + lane * 16;
#pragma unroll
    for (int q = 0; q < 4; q++) {
        float4 v = hp[q];
        asm volatile("red.global.add.v4.f32 [%0], {%1, %2, %3, %4};"
                     :: "l"(op + q * 4), "f"(v.x * w), "f"(v.y * w),
                        "f"(v.z * w), "f"(v.w * w)
                     : "memory");
    }
}

// ---------------- final semantic attention + pool + linear ------------------
__global__ void final_kernel(const float* __restrict__ qsem,
                             const float* __restrict__ linw,
                             const float* __restrict__ linb,
                             float* __restrict__ out) {
    __shared__ float sh[DD];
    __shared__ float sv[2];
    int f = threadIdx.x;
    const float invN = 1.0f / (float)NN;
    float q = qsem[f];
    float v0 = g_ksum[f] * invN * q;
    float v1 = g_ksum[DD + f] * invN * q;

    sh[f] = v0; __syncthreads();
    for (int s = 256; s > 0; s >>= 1) { if (f < s) sh[f] += sh[f + s]; __syncthreads(); }
    if (f == 0) sv[0] = sh[0];
    __syncthreads();
    sh[f] = v1; __syncthreads();
    for (int s = 256; s > 0; s >>= 1) { if (f < s) sh[f] += sh[f + s]; __syncthreads(); }
    if (f == 0) sv[1] = sh[0];
    __syncthreads();

    float s0 = sv[0], s1 = sv[1];
    float mx = fmaxf(s0, s1);
    float e0 = expf(s0 - mx), e1 = expf(s1 - mx);
    float sem0 = e0 / (e0 + e1), sem1 = e1 / (e0 + e1);

    float pooled = (sem0 * g_musum[f] + sem1 * g_musum[DD + f]) * invN;
    float w0 = pooled * linw[f * 2 + 0];
    float w1 = pooled * linw[f * 2 + 1];

    sh[f] = w0; __syncthreads();
    for (int s = 256; s > 0; s >>= 1) { if (f < s) sh[f] += sh[f + s]; __syncthreads(); }
    if (f == 0) out[0] = sh[0] + linb[0];
    __syncthreads();
    sh[f] = w1; __syncthreads();
    for (int s = 256; s > 0; s >>= 1) { if (f < s) sh[f] += sh[f + s]; __syncthreads(); }
    if (f == 0) out[1] = sh[0] + linb[1];
}

// ---------------- host launcher ---------------------------------------------
extern "C" void kernel_launch(void* const* d_in, const int* in_sizes, int n_in,
                              void* d_out, int out_size) {
    const float* x_o  = (const float*)d_in[0];
    const float* x_e  = (const float*)d_in[1];
    const int*   e2o  = (const int*)d_in[2];
    const int*   o2o  = (const int*)d_in[3];
    const float* powm = (const float*)d_in[4];
    const float* pob  = (const float*)d_in[5];
    const float* pewm = (const float*)d_in[6];
    const float* peb  = (const float*)d_in[7];
    const float* a_s_e2o = (const float*)d_in[8];
    const float* a_d_e2o = (const float*)d_in[9];
    const float* a_s_o2o = (const float*)d_in[10];
    const float* a_d_o2o = (const float*)d_in[11];
    const float* klw  = (const float*)d_in[12];
    const float* klb  = (const float*)d_in[13];
    const float* qsem = (const float*)d_in[14];
    const float* linw = (const float*)d_in[15];
    const float* linb = (const float*)d_in[16];
    float* out = (float*)d_out;

    void* p;
    float *h_o, *h_e, *out0, *out1, *a_se, *a_de, *a_so, *a_do, *denom, *ebuf, *ksum, *musum;
    __nv_bfloat16 *Ab, *Wb;
    unsigned* amax;
    cudaGetSymbolAddress(&p, g_h_o);  h_o  = (float*)p;
    cudaGetSymbolAddress(&p, g_h_e);  h_e  = (float*)p;
    cudaGetSymbolAddress(&p, g_out0); out0 = (float*)p;
    cudaGetSymbolAddress(&p, g_out1); out1 = (float*)p;
    cudaGetSymbolAddress(&p, g_Ab);   Ab   = (__nv_bfloat16*)p;
    cudaGetSymbolAddress(&p, g_Wb);   Wb   = (__nv_bfloat16*)p;
    cudaGetSymbolAddress(&p, g_a_se); a_se = (float*)p;
    cudaGetSymbolAddress(&p, g_a_de); a_de = (float*)p;
    cudaGetSymbolAddress(&p, g_a_so); a_so = (float*)p;
    cudaGetSymbolAddress(&p, g_a_do); a_do = (float*)p;
    cudaGetSymbolAddress(&p, g_amax); amax = (unsigned*)p;
    cudaGetSymbolAddress(&p, g_denom); denom = (float*)p;
    cudaGetSymbolAddress(&p, g_ebuf); ebuf = (float*)p;
    cudaGetSymbolAddress(&p, g_ksum); ksum = (float*)p;
    cudaGetSymbolAddress(&p, g_musum); musum = (float*)p;

    const long ND = (long)NN * DD;
    dim3 tcgrid(DD / GBN, (NN + GBM - 1) / GBM);   // (4, 782)

    // ---- GEMM 1: h_o = x_o @ proj_o_w + b ----
    conv_bf<<<256, 256>>>(powm, Wb, DD * DD);
    conv_bf<<<2048, 256>>>(x_o, Ab, ND);
    zero_buf<<<4096, 256>>>(out0, ND);
    zero_buf<<<4096, 256>>>(out1, ND);
    zero_buf<<<4, 256>>>(ksum, 2 * DD);
    gemm_bf<0><<<tcgrid, 256>>>(Ab, Wb, pob, h_o, NN, nullptr);

    // ---- GEMM 2: h_e = x_e @ proj_e_w + b ----
    conv_bf<<<256, 256>>>(pewm, Wb, DD * DD);
    conv_bf<<<2048, 256>>>(x_e, Ab, ND);
    zero_buf<<<4, 256>>>(musum, 2 * DD);
    gemm_bf<0><<<tcgrid, 256>>>(Ab, Wb, peb, h_e, NN, nullptr);

    int ah_blocks = (NN * 32 + 255) / 256;
    int eh_blocks = (EE * HH + 255) / 256;
    int sc_blocks = (EE * 32 + 255) / 256;
    int ie_blocks = (NN * HH + 255) / 256;

    // ---- attention dots ----
    compute_ah3<<<ah_blocks, 256>>>(h_o, a_d_e2o, a_de, a_s_o2o, a_so, a_d_o2o, a_do, NN);
    compute_ah3<<<ah_blocks, 256>>>(h_e, a_s_e2o, a_se, nullptr, nullptr, nullptr, nullptr, NN);

    // ---- metapath 0: entity -> openie ----
    init_edge_state<<<ie_blocks, 256>>>(amax, denom, NN * HH);
    edge_alpha_max<<<eh_blocks, 256>>>(e2o, e2o + EE, a_se, a_de, ebuf, amax, EE);
    edge_exp_sum<<<eh_blocks, 256>>>(e2o + EE, ebuf, amax, denom, EE);
    edge_scatter<<<sc_blocks, 256>>>(e2o, e2o + EE, h_e, ebuf, denom, out0, EE);

    // ---- metapath 1: openie -> openie ----
    init_edge_state<<<ie_blocks, 256>>>(amax, denom, NN * HH);
    edge_alpha_max<<<eh_blocks, 256>>>(o2o, o2o + EE, a_so, a_do, ebuf, amax, EE);
    edge_exp_sum<<<eh_blocks, 256>>>(o2o + EE, ebuf, amax, denom, EE);
    edge_scatter<<<sc_blocks, 256>>>(o2o, o2o + EE, h_o, ebuf, denom, out1, EE);

    // ---- semantic attention: ksum_m = sum_n tanh(relu(out_m) @ klw + b) ----
    conv_bf<<<256, 256>>>(klw, Wb, DD * DD);
    convmu<<<128, 512>>>(out0, Ab, musum, NN);          // relu+bf16+column sums
    gemm_bf<1><<<tcgrid, 256>>>(Ab, Wb, klb, nullptr, NN, ksum);
    convmu<<<128, 512>>>(out1, Ab, musum + DD, NN);
    gemm_bf<1><<<tcgrid, 256>>>(Ab, Wb, klb, nullptr, NN, ksum + DD);

    // ---- softmax over metapaths, pool, final linear ----
    final_kernel<<<1, 512>>>(qsem, linw, linb, out);
}

// round 10
// speedup vs baseline: 1.9987x; 1.0358x over previous
#include <cuda_runtime.h>
#include <cuda_bf16.h>
#include <cstdint>
#include <math.h>
#include <mma.h>

using namespace nvcuda;

#define NN 100000
#define EE 150000
#define DD 512
#define HH 8

#define GBM 128
#define GBN 128
#define GBK 32
#define APADE 8    // As row stride 40 bf16 = 80B = 5x16B (odd -> LDSM conflict-free)
#define BPADE 8    // Bs row stride 136 bf16 = 272B = 17x16B (odd -> LDSM conflict-free)

// ---------------- scratch ---------------------------------------------------
__device__ float g_h_o[(size_t)NN * DD];
__device__ float g_h_e[(size_t)NN * DD];
__device__ float g_out0[(size_t)NN * DD];
__device__ float g_out1[(size_t)NN * DD];
__device__ __nv_bfloat16 g_Ab[(size_t)NN * DD];   // bf16 A operand (reused 4x)
__device__ __nv_bfloat16 g_Wb[DD * DD];           // bf16 W operand (reused 3x)
__device__ float g_a_se[NN * HH];
__device__ float g_a_de[NN * HH];
__device__ float g_a_so[NN * HH];
__device__ float g_a_do[NN * HH];
__device__ unsigned g_amax[NN * HH];
__device__ float g_denom[NN * HH];
__device__ float g_ebuf[EE * HH];
__device__ float g_ksum[2 * DD];
__device__ float g_musum[2 * DD];

// ---------------- helpers ---------------------------------------------------
__device__ __forceinline__ unsigned mapf(float f) {
    unsigned u = __float_as_uint(f);
    return (u & 0x80000000u) ? ~u : (u | 0x80000000u);
}
__device__ __forceinline__ float unmapf(unsigned u) {
    return __uint_as_float((u & 0x80000000u) ? (u & 0x7FFFFFFFu) : ~u);
}

__global__ void zero_buf(float* p, long n) {
    long i = (long)blockIdx.x * blockDim.x + threadIdx.x;
    long stride = (long)gridDim.x * blockDim.x;
    for (; i < n; i += stride) p[i] = 0.0f;
}

__global__ void init_edge_state(unsigned* amax, float* denom, int n) {
    int i = blockIdx.x * blockDim.x + threadIdx.x;
    if (i < n) { amax[i] = 0x007FFFFFu; denom[i] = 0.0f; }  // mapf(-inf)
}

// ---------------- fp32 -> bf16 conversion (vectorized) ----------------------
__global__ void conv_bf(const float* __restrict__ src,
                        __nv_bfloat16* __restrict__ dst, long n) {
    long i = ((long)blockIdx.x * blockDim.x + threadIdx.x) * 4;
    long stride = (long)gridDim.x * blockDim.x * 4;
    for (; i < n; i += stride) {
        float4 v = *(const float4*)(src + i);
        *(__nv_bfloat162*)(dst + i)     = __floats2bfloat162_rn(v.x, v.y);
        *(__nv_bfloat162*)(dst + i + 2) = __floats2bfloat162_rn(v.z, v.w);
    }
}

// ---------------- fused relu + bf16 convert + column sums -------------------
__global__ void convmu(const float* __restrict__ outb,
                       __nv_bfloat16* __restrict__ dst,
                       float* __restrict__ musum, int M) {
    int f = threadIdx.x;                   // 512 threads = columns
    int chunk = (M + gridDim.x - 1) / gridDim.x;
    int r0 = blockIdx.x * chunk;
    int r1 = min(M, r0 + chunk);
    float acc = 0.f;
    for (int r = r0; r < r1; r++) {
        float v = fmaxf(outb[(size_t)r * DD + f], 0.f);
        acc += v;
        dst[(size_t)r * DD + f] = __float2bfloat16(v);
    }
    atomicAdd(&musum[f], acc);
}

// ---------------- BF16 TC GEMM, 2-stage cp.async, static smem ---------------
// MODE 0: C = A@W + bias (stored fp32).
// MODE 1: epilogue accumulates sum_rows tanh(acc+bias) into ksum_out.
template <int MODE>
__global__ void __launch_bounds__(256) gemm_bf(
        const __nv_bfloat16* __restrict__ A, const __nv_bfloat16* __restrict__ W,
        const float* __restrict__ bias, float* __restrict__ C, int M,
        float* __restrict__ ksum_out) {
    __shared__ __nv_bfloat16 As[2][GBM][GBK + APADE];   // 2 x 128 x 40
    __shared__ __nv_bfloat16 Bs[2][GBK][GBN + BPADE];   // 2 x 32 x 136
    __shared__ float stage[8][16][20];
    __shared__ float ksred[GBN];

    int tid = threadIdx.x;
    int wid = tid >> 5;
    int lane = tid & 31;
    int warp_m = wid & 3;
    int warp_n = wid >> 2;
    int m0 = blockIdx.y * GBM;
    int n0 = blockIdx.x * GBN;
    int wm0 = warp_m * 32;
    int wn0 = warp_n * 64;

    if (MODE == 1 && tid < GBN) ksred[tid] = 0.0f;

    // A tile: 128x32 bf16 = 512 x 16B chunks; B tile: 32x128 bf16 = 512 chunks
    auto load_stage = [&](int s, int k0) {
#pragma unroll
        for (int it = 0; it < 2; it++) {
            int idx = tid + it * 256;
            int ar = idx >> 2, ac = (idx & 3) * 8;
            int gm = m0 + ar;
            const __nv_bfloat16* srcA =
                A + (size_t)(gm < M ? gm : M - 1) * DD + k0 + ac;
            uint32_t dstA = (uint32_t)__cvta_generic_to_shared(&As[s][ar][ac]);
            int szA = (gm < M) ? 16 : 0;
            asm volatile("cp.async.cg.shared.global [%0], [%1], 16, %2;"
                         :: "r"(dstA), "l"(srcA), "r"(szA));
            int br = idx >> 4, bc = (idx & 15) * 8;
            const __nv_bfloat16* srcB = W + (size_t)(k0 + br) * DD + n0 + bc;
            uint32_t dstB = (uint32_t)__cvta_generic_to_shared(&Bs[s][br][bc]);
            asm volatile("cp.async.cg.shared.global [%0], [%1], 16, 16;"
                         :: "r"(dstB), "l"(srcB));
        }
    };

    wmma::fragment<wmma::accumulator, 16, 16, 16, float> acc[2][4];
#pragma unroll
    for (int i = 0; i < 2; i++)
#pragma unroll
        for (int j = 0; j < 4; j++) wmma::fill_fragment(acc[i][j], 0.0f);

    load_stage(0, 0);
    asm volatile("cp.async.commit_group;");

    int sbuf = 0;
    for (int k0 = 0; k0 < DD; k0 += GBK) {
        if (k0 + GBK < DD) load_stage(sbuf ^ 1, k0 + GBK);
        asm volatile("cp.async.commit_group;");
        asm volatile("cp.async.wait_group 1;");
        __syncthreads();

#pragma unroll
        for (int kk = 0; kk < GBK; kk += 16) {
            wmma::fragment<wmma::matrix_a, 16, 16, 16, __nv_bfloat16,
                           wmma::row_major> af[2];
            wmma::fragment<wmma::matrix_b, 16, 16, 16, __nv_bfloat16,
                           wmma::row_major> bf[4];
#pragma unroll
            for (int i = 0; i < 2; i++)
                wmma::load_matrix_sync(af[i], &As[sbuf][wm0 + i * 16][kk],
                                       GBK + APADE);
#pragma unroll
            for (int j = 0; j < 4; j++)
                wmma::load_matrix_sync(bf[j], &Bs[sbuf][kk][wn0 + j * 16],
                                       GBN + BPADE);
#pragma unroll
            for (int i = 0; i < 2; i++)
#pragma unroll
                for (int j = 0; j < 4; j++)
                    wmma::mma_sync(acc[i][j], af[i], bf[j], acc[i][j]);
        }
        __syncthreads();
        sbuf ^= 1;
    }

    // ---------------- epilogue ----------------
    int r = lane >> 1;
    int cbase = (lane & 1) * 8;
#pragma unroll
    for (int i = 0; i < 2; i++) {
#pragma unroll
        for (int j = 0; j < 4; j++) {
            wmma::store_matrix_sync(&stage[wid][0][0], acc[i][j], 20,
                                    wmma::mem_row_major);
            __syncwarp();
            int grow = m0 + wm0 + i * 16 + r;
            int gcol = n0 + wn0 + j * 16 + cbase;
            if (grow < M) {
                float4 v1 = *(const float4*)(&stage[wid][r][cbase]);
                float4 v2 = *(const float4*)(&stage[wid][r][cbase + 4]);
                float4 b1 = *(const float4*)(bias + gcol);
                float4 b2 = *(const float4*)(bias + gcol + 4);
                v1.x += b1.x; v1.y += b1.y; v1.z += b1.z; v1.w += b1.w;
                v2.x += b2.x; v2.y += b2.y; v2.z += b2.z; v2.w += b2.w;
                if (MODE == 0) {
                    *(float4*)(C + (size_t)grow * DD + gcol) = v1;
                    *(float4*)(C + (size_t)grow * DD + gcol + 4) = v2;
                } else {
                    int lc = wn0 + j * 16 + cbase;
                    atomicAdd(&ksred[lc + 0], tanhf(v1.x));
                    atomicAdd(&ksred[lc + 1], tanhf(v1.y));
                    atomicAdd(&ksred[lc + 2], tanhf(v1.z));
                    atomicAdd(&ksred[lc + 3], tanhf(v1.w));
                    atomicAdd(&ksred[lc + 4], tanhf(v2.x));
                    atomicAdd(&ksred[lc + 5], tanhf(v2.y));
                    atomicAdd(&ksred[lc + 6], tanhf(v2.z));
                    atomicAdd(&ksred[lc + 7], tanhf(v2.w));
                }
            }
            __syncwarp();
        }
    }
    if (MODE == 1) {
        __syncthreads();
        if (tid < GBN) atomicAdd(&ksum_out[n0 + tid], ksred[tid]);
    }
}

// ---------------- attention dots: 1 read of h, up to 3 att pairs ------------
__global__ void compute_ah3(const float* __restrict__ hmat,
                            const float* __restrict__ att0, float* __restrict__ a0,
                            const float* __restrict__ att1, float* __restrict__ a1,
                            const float* __restrict__ att2, float* __restrict__ a2,
                            int n_nodes) {
    int gt = blockIdx.x * blockDim.x + threadIdx.x;
    int warp = gt >> 5;
    int lane = threadIdx.x & 31;
    if (warp >= n_nodes) return;
    int base = lane * 16;
    const float4* hp = (const float4*)(hmat + (size_t)warp * DD + base);
    const float4* ap0 = (const float4*)(att0 + base);
    const float4* ap1 = att1 ? (const float4*)(att1 + base) : nullptr;
    const float4* ap2 = att2 ? (const float4*)(att2 + base) : nullptr;
    float s0 = 0.f, s1 = 0.f, s2 = 0.f;
#pragma unroll
    for (int q = 0; q < 4; q++) {
        float4 hv = hp[q];
        float4 av = ap0[q];
        s0 += hv.x * av.x + hv.y * av.y + hv.z * av.z + hv.w * av.w;
        if (ap1) {
            float4 bv = ap1[q];
            s1 += hv.x * bv.x + hv.y * bv.y + hv.z * bv.z + hv.w * bv.w;
        }
        if (ap2) {
            float4 cv = ap2[q];
            s2 += hv.x * cv.x + hv.y * cv.y + hv.z * cv.z + hv.w * cv.w;
        }
    }
#pragma unroll
    for (int d = 1; d <= 2; d <<= 1) {
        s0 += __shfl_xor_sync(0xffffffffu, s0, d);
        s1 += __shfl_xor_sync(0xffffffffu, s1, d);
        s2 += __shfl_xor_sync(0xffffffffu, s2, d);
    }
    if ((lane & 3) == 0) {
        int o = warp * HH + (lane >> 2);
        a0[o] = s0;
        if (a1) a1[o] = s1;
        if (a2) a2[o] = s2;
    }
}

// ---------------- edge pass 1: alpha + segment max --------------------------
__global__ void edge_alpha_max(const int* __restrict__ src,
                               const int* __restrict__ dst,
                               const float* __restrict__ asrc,
                               const float* __restrict__ adst,
                               float* __restrict__ alpha,
                               unsigned* __restrict__ amax, int ne) {
    int i = blockIdx.x * blockDim.x + threadIdx.x;
    if (i >= ne * HH) return;
    int e = i >> 3, h = i & 7;
    float v = asrc[src[e] * HH + h] + adst[dst[e] * HH + h];
    v = (v > 0.f) ? v : 0.2f * v;
    alpha[i] = v;
    atomicMax(&amax[dst[e] * HH + h], mapf(v));
}

// ---------------- edge pass 2: exp + segment sum ----------------------------
__global__ void edge_exp_sum(const int* __restrict__ dst,
                             float* __restrict__ alpha,
                             const unsigned* __restrict__ amax,
                             float* __restrict__ denom, int ne) {
    int i = blockIdx.x * blockDim.x + threadIdx.x;
    if (i >= ne * HH) return;
    int e = i >> 3, h = i & 7;
    float ex = expf(alpha[i] - unmapf(amax[dst[e] * HH + h]));
    alpha[i] = ex;
    atomicAdd(&denom[dst[e] * HH + h], ex);
}

// ---------------- edge pass 3: weighted scatter (vector red) ----------------
__global__ void edge_scatter(const int* __restrict__ src,
                             const int* __restrict__ dst,
                             const float* __restrict__ hsrc,
                             const float* __restrict__ exbuf,
                             const float* __restrict__ denom,
                             float* __restrict__ outb, int ne) {
    int gt = blockIdx.x * blockDim.x + threadIdx.x;
    int e = gt >> 5;
    int lane = threadIdx.x & 31;
    if (e >= ne) return;
    int s = src[e], d = dst[e];
    int h = lane >> 2;
    float w = exbuf[e * HH + h] / (denom[d * HH + h] + 1e-16f);
    const float4* hp = (const float4*)(hsrc + (size_t)s * DD + lane * 16);
    float* op = outb + (size_t)d * DD + lane * 16;
#pragma unroll
    for (int q = 0; q < 4; q++) {
        float4 v = hp[q];
        asm volatile("red.global.add.v4.f32 [%0], {%1, %2, %3, %4};"
                     :: "l"(op + q * 4), "f"(v.x * w), "f"(v.y * w),
                        "f"(v.z * w), "f"(v.w * w)
                     : "memory");
    }
}

// ---------------- final semantic attention + pool + linear ------------------
__global__ void final_kernel(const float* __restrict__ qsem,
                             const float* __restrict__ linw,
                             const float* __restrict__ linb,
                             float* __restrict__ out) {
    __shared__ float sh[DD];
    __shared__ float sv[2];
    int f = threadIdx.x;
    const float invN = 1.0f / (float)NN;
    float q = qsem[f];
    float v0 = g_ksum[f] * invN * q;
    float v1 = g_ksum[DD + f] * invN * q;

    sh[f] = v0; __syncthreads();
    for (int s = 256; s > 0; s >>= 1) { if (f < s) sh[f] += sh[f + s]; __syncthreads(); }
    if (f == 0) sv[0] = sh[0];
    __syncthreads();
    sh[f] = v1; __syncthreads();
    for (int s = 256; s > 0; s >>= 1) { if (f < s) sh[f] += sh[f + s]; __syncthreads(); }
    if (f == 0) sv[1] = sh[0];
    __syncthreads();

    float s0 = sv[0], s1 = sv[1];
    float mx = fmaxf(s0, s1);
    float e0 = expf(s0 - mx), e1 = expf(s1 - mx);
    float sem0 = e0 / (e0 + e1), sem1 = e1 / (e0 + e1);

    float pooled = (sem0 * g_musum[f] + sem1 * g_musum[DD + f]) * invN;
    float w0 = pooled * linw[f * 2 + 0];
    float w1 = pooled * linw[f * 2 + 1];

    sh[f] = w0; __syncthreads();
    for (int s = 256; s > 0; s >>= 1) { if (f < s) sh[f] += sh[f + s]; __syncthreads(); }
    if (f == 0) out[0] = sh[0] + linb[0];
    __syncthreads();
    sh[f] = w1; __syncthreads();
    for (int s = 256; s > 0; s >>= 1) { if (f < s) sh[f] += sh[f + s]; __syncthreads(); }
    if (f == 0) out[1] = sh[0] + linb[1];
}

// ---------------- host launcher ---------------------------------------------
extern "C" void kernel_launch(void* const* d_in, const int* in_sizes, int n_in,
                              void* d_out, int out_size) {
    const float* x_o  = (const float*)d_in[0];
    const float* x_e  = (const float*)d_in[1];
    const int*   e2o  = (const int*)d_in[2];
    const int*   o2o  = (const int*)d_in[3];
    const float* powm = (const float*)d_in[4];
    const float* pob  = (const float*)d_in[5];
    const float* pewm = (const float*)d_in[6];
    const float* peb  = (const float*)d_in[7];
    const float* a_s_e2o = (const float*)d_in[8];
    const float* a_d_e2o = (const float*)d_in[9];
    const float* a_s_o2o = (const float*)d_in[10];
    const float* a_d_o2o = (const float*)d_in[11];
    const float* klw  = (const float*)d_in[12];
    const float* klb  = (const float*)d_in[13];
    const float* qsem = (const float*)d_in[14];
    const float* linw = (const float*)d_in[15];
    const float* linb = (const float*)d_in[16];
    float* out = (float*)d_out;

    void* p;
    float *h_o, *h_e, *out0, *out1, *a_se, *a_de, *a_so, *a_do, *denom, *ebuf, *ksum, *musum;
    __nv_bfloat16 *Ab, *Wb;
    unsigned* amax;
    cudaGetSymbolAddress(&p, g_h_o);  h_o  = (float*)p;
    cudaGetSymbolAddress(&p, g_h_e);  h_e  = (float*)p;
    cudaGetSymbolAddress(&p, g_out0); out0 = (float*)p;
    cudaGetSymbolAddress(&p, g_out1); out1 = (float*)p;
    cudaGetSymbolAddress(&p, g_Ab);   Ab   = (__nv_bfloat16*)p;
    cudaGetSymbolAddress(&p, g_Wb);   Wb   = (__nv_bfloat16*)p;
    cudaGetSymbolAddress(&p, g_a_se); a_se = (float*)p;
    cudaGetSymbolAddress(&p, g_a_de); a_de = (float*)p;
    cudaGetSymbolAddress(&p, g_a_so); a_so = (float*)p;
    cudaGetSymbolAddress(&p, g_a_do); a_do = (float*)p;
    cudaGetSymbolAddress(&p, g_amax); amax = (unsigned*)p;
    cudaGetSymbolAddress(&p, g_denom); denom = (float*)p;
    cudaGetSymbolAddress(&p, g_ebuf); ebuf = (float*)p;
    cudaGetSymbolAddress(&p, g_ksum); ksum = (float*)p;
    cudaGetSymbolAddress(&p, g_musum); musum = (float*)p;

    const long ND = (long)NN * DD;
    dim3 tcgrid(DD / GBN, (NN + GBM - 1) / GBM);   // (4, 782)

    // ---- GEMM 1: h_o = x_o @ proj_o_w + b ----
    conv_bf<<<256, 256>>>(powm, Wb, DD * DD);
    conv_bf<<<2048, 256>>>(x_o, Ab, ND);
    zero_buf<<<4096, 256>>>(out0, ND);
    zero_buf<<<4096, 256>>>(out1, ND);
    zero_buf<<<4, 256>>>(ksum, 2 * DD);
    gemm_bf<0><<<tcgrid, 256>>>(Ab, Wb, pob, h_o, NN, nullptr);

    // ---- GEMM 2: h_e = x_e @ proj_e_w + b ----
    conv_bf<<<256, 256>>>(pewm, Wb, DD * DD);
    conv_bf<<<2048, 256>>>(x_e, Ab, ND);
    zero_buf<<<4, 256>>>(musum, 2 * DD);
    gemm_bf<0><<<tcgrid, 256>>>(Ab, Wb, peb, h_e, NN, nullptr);

    int ah_blocks = (NN * 32 + 255) / 256;
    int eh_blocks = (EE * HH + 255) / 256;
    int sc_blocks = (EE * 32 + 255) / 256;
    int ie_blocks = (NN * HH + 255) / 256;

    // ---- attention dots ----
    compute_ah3<<<ah_blocks, 256>>>(h_o, a_d_e2o, a_de, a_s_o2o, a_so, a_d_o2o, a_do, NN);
    compute_ah3<<<ah_blocks, 256>>>(h_e, a_s_e2o, a_se, nullptr, nullptr, nullptr, nullptr, NN);

    // ---- metapath 0: entity -> openie ----
    init_edge_state<<<ie_blocks, 256>>>(amax, denom, NN * HH);
    edge_alpha_max<<<eh_blocks, 256>>>(e2o, e2o + EE, a_se, a_de, ebuf, amax, EE);
    edge_exp_sum<<<eh_blocks, 256>>>(e2o + EE, ebuf, amax, denom, EE);
    edge_scatter<<<sc_blocks, 256>>>(e2o, e2o + EE, h_e, ebuf, denom, out0, EE);

    // ---- metapath 1: openie -> openie ----
    init_edge_state<<<ie_blocks, 256>>>(amax, denom, NN * HH);
    edge_alpha_max<<<eh_blocks, 256>>>(o2o, o2o + EE, a_so, a_do, ebuf, amax, EE);
    edge_exp_sum<<<eh_blocks, 256>>>(o2o + EE, ebuf, amax, denom, EE);
    edge_scatter<<<sc_blocks, 256>>>(o2o, o2o + EE, h_o, ebuf, denom, out1, EE);

    // ---- semantic attention: ksum_m = sum_n tanh(relu(out_m) @ klw + b) ----
    conv_bf<<<256, 256>>>(klw, Wb, DD * DD);
    convmu<<<128, 512>>>(out0, Ab, musum, NN);
    gemm_bf<1><<<tcgrid, 256>>>(Ab, Wb, klb, nullptr, NN, ksum);
    convmu<<<128, 512>>>(out1, Ab, musum + DD, NN);
    gemm_bf<1><<<tcgrid, 256>>>(Ab, Wb, klb, nullptr, NN, ksum + DD);

    // ---- softmax over metapaths, pool, final linear ----
    final_kernel<<<1, 512>>>(qsem, linw, linb, out);
}